// round 15
// baseline (speedup 1.0000x reference)
#include <cuda_runtime.h>
#include <cuda_bf16.h>
#include <math.h>
#include <stdint.h>

typedef __nv_bfloat16 bf16;

#define IMG 512
#define CIN_ 3
#define DMODEL 256
#define KCODES 8192
#define LAYERS 6
#define HEADS 8
#define FFDIM 1024
#define BATCH 32
#define NPATCH 256
#define ROWS 8192
#define NXHAT (BATCH * 3 * 256 * 256)

// ---------------------------------------------------------------------------
// Static scratch
// ---------------------------------------------------------------------------
__device__ float g_h[ROWS * DMODEL];
__device__ float g_proj[ROWS * DMODEL];
__device__ float g_f2[ROWS * DMODEL];
__device__ float g_cbn[KCODES];
__device__ float g_tv[ROWS * 64];
__device__ int   g_ti[ROWS * 64];
__device__ float g_rowloss[ROWS];

__device__ bf16 g_xb[BATCH * 3 * IMG * IMG];
__device__ bf16 g_pwb[DMODEL * 3072];
__device__ bf16 g_qkvwb[LAYERS * 768 * 256];
__device__ bf16 g_outwb[LAYERS * 256 * 256];
__device__ bf16 g_ff1wb[LAYERS * 1024 * 256];
__device__ bf16 g_ff2wb[LAYERS * 256 * 1024];
__device__ bf16 g_cbb[KCODES * DMODEL];
__device__ bf16 g_wpb[1703936];                 // parity weights, 3 layers
__device__ bf16 g_hb[ROWS * DMODEL];
__device__ bf16 g_qkvb[ROWS * 768];
__device__ bf16 g_attnb[ROWS * DMODEL];
__device__ bf16 g_midb[ROWS * FFDIM];
__device__ bf16 g_qdecb[ROWS * DMODEL];         // NHWC (b,16,16,256)
__device__ bf16 g_y0b[BATCH * 32 * 32 * 256];   // NHWC
__device__ bf16 g_y1b[BATCH * 64 * 64 * 128];   // NHWC
__device__ bf16 g_y2b[BATCH * 128 * 128 * 64];  // NHWC

#define WP0 0
#define WP1 1048576
#define WP2 1572864

// ---------------------------------------------------------------------------
// Helpers
// ---------------------------------------------------------------------------
__device__ __forceinline__ float gelu_exact(float v) {
    return 0.5f * v * (1.0f + erff(v * 0.7071067811865476f));
}
__device__ __forceinline__ uint32_t b2pack(float x, float y) {
    __nv_bfloat162 h = __floats2bfloat162_rn(x, y);
    return *reinterpret_cast<uint32_t*>(&h);
}
__device__ __forceinline__ uint32_t smem_u32(const void* p) {
    uint32_t r;
    asm("{ .reg .u64 t; cvta.to.shared.u64 t, %1; cvt.u32.u64 %0, t; }"
        : "=r"(r) : "l"(p));
    return r;
}
__device__ __forceinline__ void ldm_x4(uint32_t& r0, uint32_t& r1, uint32_t& r2,
                                       uint32_t& r3, uint32_t addr) {
    asm volatile("ldmatrix.sync.aligned.m8n8.x4.shared.b16 {%0,%1,%2,%3}, [%4];"
                 : "=r"(r0), "=r"(r1), "=r"(r2), "=r"(r3) : "r"(addr));
}
__device__ __forceinline__ void mma16816(float* c, const uint32_t* a,
                                         uint32_t b0, uint32_t b1) {
    asm volatile(
        "mma.sync.aligned.m16n8k16.row.col.f32.bf16.bf16.f32 "
        "{%0,%1,%2,%3},{%4,%5,%6,%7},{%8,%9},{%0,%1,%2,%3};"
        : "+f"(c[0]), "+f"(c[1]), "+f"(c[2]), "+f"(c[3])
        : "r"(a[0]), "r"(a[1]), "r"(a[2]), "r"(a[3]), "r"(b0), "r"(b1));
}
__device__ __forceinline__ void cpa16(uint32_t dst, const void* src, int sz) {
    asm volatile("cp.async.cg.shared.global [%0], [%1], 16, %2;"
                 :: "r"(dst), "l"(src), "r"(sz) : "memory");
}
__device__ __forceinline__ void cp_commit() {
    asm volatile("cp.async.commit_group;" ::: "memory");
}
template<int W> __device__ __forceinline__ void cp_wait() {
    asm volatile("cp.async.wait_group %0;" :: "n"(W) : "memory");
}

// ---------------------------------------------------------------------------
// bf16 cp.async 3-stage tensor-core GEMM (K-chunk 32, pitch 40).
//   C[M,N] = A @ B^T
//   AMODE 0: A bf16 row-major M x K.
//   AMODE 2: implicit conv_t im2col over NHWC bf16 (Cin=2^cinlg, Hin=2^hinlg);
//            parity = blockIdx.z; B offset by parity internally.
//   AMODE 3: implicit patch im2col over bf16 x (B,3,512,512).
// EPI: 1 +bias fp32 C (+bf16 Cb if non-null) | 2 +bias+GELU bf16 | 5 +bias bf16 |
//      3 VQ argmin | 4 +bias+ReLU scatter to bf16 NHWC at parity offset.
// MB: min blocks per SM (3 for BN=64, 2 for BN=128).
// ---------------------------------------------------------------------------
template<int EPI, int AMODE, int BN_, int MB>
__global__ void __launch_bounds__(256, MB) gemm_cp(
    const bf16* __restrict__ A, const bf16* __restrict__ B,
    const float* __restrict__ bias, float* __restrict__ C,
    bf16* __restrict__ Cb, int* __restrict__ Ci,
    int M, int N, int K, int hinlg, int cinlg)
{
    constexpr int NT = BN_ / 16;
    extern __shared__ __align__(16) char dynsmem[];
    bf16* Asp = (bf16*)dynsmem;                 // [3][128][40]
    bf16* Bsp = Asp + 3 * 128 * 40;             // [3][BN_][40]
    float* s_val = (float*)(Bsp + 3 * BN_ * 40);
    int*   s_idx = (int*)(s_val + 256);

    const int tid  = threadIdx.x;
    const int lane = tid & 31, warp = tid >> 5;
    const int wm = warp >> 1, wn = warp & 1;
    const int g = lane >> 2, tig = lane & 3;
    const int row0 = blockIdx.y * 128;
    const int col0 = blockIdx.x * BN_;
    const int m_off = wm * 32;
    const int n_off = wn * (BN_ / 2);
    const int pyx = (AMODE == 2) ? blockIdx.z : 0;
    if constexpr (AMODE == 2) B += (size_t)pyx * N * K;

    const uint32_t as_base = smem_u32(Asp);
    const uint32_t bs_base = smem_u32(Bsp);
    const int a_ld_row = lane & 15;
    const int a_ld_col = (lane >> 4) * 8;
    const int b_ld_row = (lane & 7) + ((lane & 16) ? 8 : 0);
    const int b_ld_col = (lane & 8) ? 8 : 0;

    const int cp_m = tid >> 1;
    const int cp_c = (tid & 1) * 16;

    int am_b = 0, am_jy = 0, am_jx = 0, Hin = 0;
    if constexpr (AMODE == 2) {
        Hin = 1 << hinlg;
        int m = row0 + cp_m;
        am_b = m >> (2 * hinlg);
        int rem = m & ((1 << (2 * hinlg)) - 1);
        am_jy = rem >> hinlg;
        am_jx = rem & (Hin - 1);
    } else if constexpr (AMODE == 3) {
        int m = row0 + cp_m;
        am_b = m >> 8;
        int n = m & 255;
        am_jy = n >> 4;
        am_jx = n & 15;
    }

    float acc[2][NT][4];
#pragma unroll
    for (int i = 0; i < 2; i++)
#pragma unroll
        for (int j = 0; j < NT; j++)
#pragma unroll
            for (int k = 0; k < 4; k++) acc[i][j][k] = 0.f;

    auto copyTile = [&](int buf, int t) {
        const int k0 = t * 32;
        uint32_t adst = as_base + ((uint32_t)(buf * 128 + cp_m) * 40 + cp_c) * 2;
        if constexpr (AMODE == 0) {
            const bf16* s = A + (size_t)(row0 + cp_m) * K + k0 + cp_c;
            cpa16(adst, s, 16);
            cpa16(adst + 16, s + 8, 16);
        } else if constexpr (AMODE == 3) {
            int c  = k0 >> 10;
            int py = (k0 & 1023) >> 5;
            const bf16* s = A + (((size_t)(am_b * 3 + c) * IMG + am_jy * 32 + py) * IMG
                                 + am_jx * 32 + cp_c);
            cpa16(adst, s, 16);
            cpa16(adst + 16, s + 8, 16);
        } else {
            int dd = k0 >> cinlg;
            int ci0 = (k0 & ((1 << cinlg) - 1)) + cp_c;
            int dy = dd >> 1, dx = dd & 1;
            int iy = am_jy - 1 + (pyx >> 1) + dy;
            int ix = am_jx - 1 + (pyx & 1) + dx;
            bool ok = (iy >= 0) & (iy < Hin) & (ix >= 0) & (ix < Hin);
            const bf16* s = ok ? (A + ((((size_t)am_b << hinlg) + iy << hinlg) + ix << cinlg) + ci0)
                               : A;
            int sz = ok ? 16 : 0;
            cpa16(adst, s, sz);
            cpa16(adst + 16, ok ? (s + 8) : s, sz);
        }
        if constexpr (BN_ == 128) {
            uint32_t bdst = bs_base + ((uint32_t)(buf * BN_ + cp_m) * 40 + cp_c) * 2;
            const bf16* s = B + (size_t)(col0 + cp_m) * K + k0 + cp_c;
            cpa16(bdst, s, 16);
            cpa16(bdst + 16, s + 8, 16);
        } else {
            uint32_t bdst = bs_base + ((uint32_t)(buf * BN_ + (tid >> 2)) * 40 + (tid & 3) * 8) * 2;
            const bf16* s = B + (size_t)(col0 + (tid >> 2)) * K + k0 + (tid & 3) * 8;
            cpa16(bdst, s, 16);
        }
    };

    const int nk = K >> 5;
    copyTile(0, 0); cp_commit();
    copyTile(1, 1); cp_commit();

    int cur = 0, wr = 2;
    for (int t = 0; t < nk; t++) {
        cp_wait<1>();
        __syncthreads();
        if (t + 2 < nk) copyTile(wr, t + 2);
        cp_commit();
#pragma unroll
        for (int ks = 0; ks < 2; ks++) {
            uint32_t af[2][4];
#pragma unroll
            for (int mt = 0; mt < 2; mt++) {
                uint32_t addr = as_base +
                    ((uint32_t)(cur * 128 + m_off + mt * 16 + a_ld_row) * 40 +
                     (uint32_t)(ks * 16 + a_ld_col)) * 2;
                ldm_x4(af[mt][0], af[mt][1], af[mt][2], af[mt][3], addr);
            }
#pragma unroll
            for (int p = 0; p < NT / 2; p++) {
                uint32_t b0, b1, b2, b3;
                uint32_t addr = bs_base +
                    ((uint32_t)(cur * BN_ + n_off + p * 16 + b_ld_row) * 40 +
                     (uint32_t)(ks * 16 + b_ld_col)) * 2;
                ldm_x4(b0, b1, b2, b3, addr);
#pragma unroll
                for (int mt = 0; mt < 2; mt++) {
                    mma16816(acc[mt][2 * p],     af[mt], b0, b1);
                    mma16816(acc[mt][2 * p + 1], af[mt], b2, b3);
                }
            }
        }
        cur = (cur == 2) ? 0 : cur + 1;
        wr  = (wr == 2) ? 0 : wr + 1;
    }

    if constexpr (EPI == 1 || EPI == 2 || EPI == 5) {
#pragma unroll
        for (int mt = 0; mt < 2; mt++)
#pragma unroll
            for (int nt = 0; nt < NT; nt++) {
                int cc = col0 + n_off + nt * 8 + tig * 2;
                float b0v = bias[cc], b1v = bias[cc + 1];
#pragma unroll
                for (int half = 0; half < 2; half++) {
                    int rr = row0 + m_off + mt * 16 + g + half * 8;
                    float v0 = acc[mt][nt][half * 2 + 0] + b0v;
                    float v1 = acc[mt][nt][half * 2 + 1] + b1v;
                    if constexpr (EPI == 2) {
                        v0 = gelu_exact(v0); v1 = gelu_exact(v1);
                        *(uint32_t*)&Cb[(size_t)rr * N + cc] = b2pack(v0, v1);
                    } else if constexpr (EPI == 5) {
                        *(uint32_t*)&Cb[(size_t)rr * N + cc] = b2pack(v0, v1);
                    } else {
                        float2 o; o.x = v0; o.y = v1;
                        *(float2*)&C[(size_t)rr * N + cc] = o;
                        if (Cb)
                            *(uint32_t*)&Cb[(size_t)rr * N + cc] = b2pack(v0, v1);
                    }
                }
            }
    } else if constexpr (EPI == 4) {
        const int Hi = 1 << hinlg, Hout = 2 << hinlg;
        const int py = pyx >> 1, px = pyx & 1;
#pragma unroll
        for (int mt = 0; mt < 2; mt++)
#pragma unroll
            for (int half = 0; half < 2; half++) {
                int rr = row0 + m_off + mt * 16 + g + half * 8;
                int b = rr >> (2 * hinlg);
                int rem = rr & ((1 << (2 * hinlg)) - 1);
                int jy = rem >> hinlg, jx = rem & (Hi - 1);
                bf16* orow = Cb + ((size_t)((b * Hout + 2 * jy + py) * Hout + 2 * jx + px)) * N;
#pragma unroll
                for (int nt = 0; nt < NT; nt++) {
                    int cc = col0 + n_off + nt * 8 + tig * 2;
                    float v0 = fmaxf(acc[mt][nt][half * 2 + 0] + bias[cc], 0.f);
                    float v1 = fmaxf(acc[mt][nt][half * 2 + 1] + bias[cc + 1], 0.f);
                    *(uint32_t*)&orow[cc] = b2pack(v0, v1);
                }
            }
    } else { // EPI 3
        float bv[4]; int bi[4];
#pragma unroll
        for (int r = 0; r < 4; r++) { bv[r] = 3.4e38f; bi[r] = 0; }
#pragma unroll
        for (int mt = 0; mt < 2; mt++)
#pragma unroll
            for (int half = 0; half < 2; half++) {
                int r = mt * 2 + half;
#pragma unroll
                for (int nt = 0; nt < NT; nt++)
#pragma unroll
                    for (int q = 0; q < 2; q++) {
                        int cc = col0 + n_off + nt * 8 + tig * 2 + q;
                        float v = bias[cc] - 2.f * acc[mt][nt][half * 2 + q];
                        if (v < bv[r] || (v == bv[r] && cc < bi[r])) { bv[r] = v; bi[r] = cc; }
                    }
            }
#pragma unroll
        for (int off = 1; off <= 2; off <<= 1)
#pragma unroll
            for (int r = 0; r < 4; r++) {
                float ov = __shfl_xor_sync(0xffffffffu, bv[r], off);
                int   oi = __shfl_xor_sync(0xffffffffu, bi[r], off);
                if (ov < bv[r] || (ov == bv[r] && oi < bi[r])) { bv[r] = ov; bi[r] = oi; }
            }
        if (tig == 0) {
#pragma unroll
            for (int r = 0; r < 4; r++) {
                int sr = m_off + (r >> 1) * 16 + g + (r & 1) * 8;
                s_val[wn * 128 + sr] = bv[r];
                s_idx[wn * 128 + sr] = bi[r];
            }
        }
        __syncthreads();
        if (tid < 128) {
            float v0 = s_val[tid], v1 = s_val[128 + tid];
            int   i0 = s_idx[tid], i1 = s_idx[128 + tid];
            if (v1 < v0 || (v1 == v0 && i1 < i0)) { v0 = v1; i0 = i1; }
            C [(size_t)(row0 + tid) * gridDim.x + blockIdx.x] = v0;
            Ci[(size_t)(row0 + tid) * gridDim.x + blockIdx.x] = i0;
        }
    }
}

// ---------------------------------------------------------------------------
// Batched fp32 -> bf16 convert: gridDim.y selects the job.
// ---------------------------------------------------------------------------
struct CvtJobs {
    const float* s[7];
    bf16* d[7];
    size_t n[7];
};
__global__ void f2bf_multi(CvtJobs j)
{
    const float* __restrict__ src = j.s[blockIdx.y];
    bf16* __restrict__ dst = j.d[blockIdx.y];
    size_t n = j.n[blockIdx.y];
    for (size_t i = ((size_t)blockIdx.x * blockDim.x + threadIdx.x) * 4; i < n;
         i += (size_t)gridDim.x * blockDim.x * 4) {
        float4 v = *(const float4*)(src + i);
        uint2 p;
        p.x = b2pack(v.x, v.y);
        p.y = b2pack(v.z, v.w);
        *(uint2*)(dst + i) = p;
    }
}

// ---------------------------------------------------------------------------
// Batched parity-weight build: gridDim.y selects the decoder layer.
// ---------------------------------------------------------------------------
struct WpJobs {
    const float* w[3];
    bf16* wp[3];
    int cin[3], cout[3];
};
__global__ void build_wp_multi(WpJobs j)
{
    const float* __restrict__ w = j.w[blockIdx.y];
    bf16* __restrict__ wp = j.wp[blockIdx.y];
    int Cin = j.cin[blockIdx.y], Cout = j.cout[blockIdx.y];
    int total = 16 * Cin * Cout;
    for (int i = blockIdx.x * blockDim.x + threadIdx.x; i < total; i += gridDim.x * blockDim.x) {
        int ci = i % Cin;
        int rest = i / Cin;
        int dd = rest & 3;
        int co = (rest >> 2) % Cout;
        int p = (rest >> 2) / Cout;
        int dy = dd >> 1, dx = dd & 1;
        int py = p >> 1, px = p & 1;
        int ky = dy ? (1 - py) : (3 - py);
        int kx = dx ? (1 - px) : (3 - px);
        wp[i] = __float2bfloat16(w[(((size_t)ci * Cout + co) * 4 + ky) * 4 + kx]);
    }
}

// ---------------------------------------------------------------------------
// Fused attention: one block per patch bt, warp = head, warp-private smem.
// ---------------------------------------------------------------------------
__global__ void __launch_bounds__(256) attn_fused(const bf16* __restrict__ qkv,
                                                  bf16* __restrict__ o)
{
    extern __shared__ float asmem[];
    const int bt = blockIdx.x;
    const int w = threadIdx.x >> 5, lane = threadIdx.x & 31;
    float* Q = asmem + w * 4224;
    float* K = Q + 1056;
    float* V = K + 1056;
    float* S = V + 1056;

#pragma unroll
    for (int s = 0; s < 32; s++) {
        size_t base = ((size_t)s * NPATCH + bt) * 768 + w * 32 + lane;
        Q[s * 33 + lane] = __bfloat162float(qkv[base]);
        K[s * 33 + lane] = __bfloat162float(qkv[base + 256]);
        V[s * 33 + lane] = __bfloat162float(qkv[base + 512]);
    }
    __syncwarp();
    {
        float Kr[32];
#pragma unroll
        for (int d = 0; d < 32; d++) Kr[d] = K[lane * 33 + d];
#pragma unroll
        for (int s = 0; s < 32; s++) {
            float acc = 0.f;
#pragma unroll
            for (int d = 0; d < 32; d++) acc = fmaf(Q[s * 33 + d], Kr[d], acc);
            S[s * 33 + lane] = acc * 0.17677669529663687f;
        }
    }
    __syncwarp();
    {
        float row[32];
        float m = -3.4e38f;
#pragma unroll
        for (int t = 0; t < 32; t++) { row[t] = S[lane * 33 + t]; m = fmaxf(m, row[t]); }
        float sum = 0.f;
#pragma unroll
        for (int t = 0; t < 32; t++) { row[t] = __expf(row[t] - m); sum += row[t]; }
        float inv = 1.f / sum;
#pragma unroll
        for (int t = 0; t < 32; t++) S[lane * 33 + t] = row[t] * inv;
    }
    __syncwarp();
    {
        float Vr[32];
#pragma unroll
        for (int t = 0; t < 32; t++) Vr[t] = V[t * 33 + lane];
#pragma unroll
        for (int s = 0; s < 32; s++) {
            float acc = 0.f;
#pragma unroll
            for (int t = 0; t < 32; t++) acc = fmaf(S[s * 33 + t], Vr[t], acc);
            o[((size_t)s * NPATCH + bt) * DMODEL + w * 32 + lane] = __float2bfloat16(acc);
        }
    }
}
#define ATTN_SMEM 135168

// ---------------------------------------------------------------------------
// Warp-per-row LayerNorm over D=256; dual fp32 + bf16 output.
// ---------------------------------------------------------------------------
__global__ void __launch_bounds__(256) ln_warp(const float* __restrict__ x,
                                               const float* __restrict__ r,
                                               const float* __restrict__ g,
                                               const float* __restrict__ b,
                                               float* __restrict__ out,
                                               bf16* __restrict__ outb)
{
    int lane = threadIdx.x & 31;
    int row = blockIdx.x * 8 + (threadIdx.x >> 5);
    const float* xr = x + (size_t)row * DMODEL;
    int d0 = lane * 4, d1 = 128 + lane * 4;
    float4 v0 = *(const float4*)(xr + d0);
    float4 v1 = *(const float4*)(xr + d1);
    if (r) {
        const float* rr = r + (size_t)row * DMODEL;
        float4 a0 = *(const float4*)(rr + d0);
        float4 a1 = *(const float4*)(rr + d1);
        v0.x += a0.x; v0.y += a0.y; v0.z += a0.z; v0.w += a0.w;
        v1.x += a1.x; v1.y += a1.y; v1.z += a1.z; v1.w += a1.w;
    }
    float s = v0.x + v0.y + v0.z + v0.w + v1.x + v1.y + v1.z + v1.w;
#pragma unroll
    for (int off = 16; off; off >>= 1) s += __shfl_xor_sync(0xffffffffu, s, off);
    float mean = s * (1.f / DMODEL);
    float c0x = v0.x - mean, c0y = v0.y - mean, c0z = v0.z - mean, c0w = v0.w - mean;
    float c1x = v1.x - mean, c1y = v1.y - mean, c1z = v1.z - mean, c1w = v1.w - mean;
    float ss = c0x*c0x + c0y*c0y + c0z*c0z + c0w*c0w
             + c1x*c1x + c1y*c1y + c1z*c1z + c1w*c1w;
#pragma unroll
    for (int off = 16; off; off >>= 1) ss += __shfl_xor_sync(0xffffffffu, ss, off);
    float inv = rsqrtf(ss * (1.f / DMODEL) + 1e-5f);
    float4 g0 = *(const float4*)(g + d0), g1 = *(const float4*)(g + d1);
    float4 b0 = *(const float4*)(b + d0), b1 = *(const float4*)(b + d1);
    float4 o0, o1;
    o0.x = c0x * inv * g0.x + b0.x; o0.y = c0y * inv * g0.y + b0.y;
    o0.z = c0z * inv * g0.z + b0.z; o0.w = c0w * inv * g0.w + b0.w;
    o1.x = c1x * inv * g1.x + b1.x; o1.y = c1y * inv * g1.y + b1.y;
    o1.z = c1z * inv * g1.z + b1.z; o1.w = c1w * inv * g1.w + b1.w;
    float* orow = out + (size_t)row * DMODEL;
    *(float4*)(orow + d0) = o0;
    *(float4*)(orow + d1) = o1;
    if (outb) {
        bf16* obr = outb + (size_t)row * DMODEL;
        uint2 p0, p1;
        p0.x = b2pack(o0.x, o0.y); p0.y = b2pack(o0.z, o0.w);
        p1.x = b2pack(o1.x, o1.y); p1.y = b2pack(o1.z, o1.w);
        *(uint2*)(obr + d0) = p0;
        *(uint2*)(obr + d1) = p1;
    }
}

// ---------------------------------------------------------------------------
// VQ helpers
// ---------------------------------------------------------------------------
__global__ void __launch_bounds__(256) cbn_kernel(const float* __restrict__ cb,
                                                  float* __restrict__ cbn)
{
    int lane = threadIdx.x & 31;
    int k = blockIdx.x * 8 + (threadIdx.x >> 5);
    const float* row = cb + (size_t)k * DMODEL;
    float s = 0.f;
#pragma unroll
    for (int i = 0; i < 2; i++) {
        float4 v = *(const float4*)(row + lane * 4 + i * 128);
        s += v.x * v.x + v.y * v.y + v.z * v.z + v.w * v.w;
    }
#pragma unroll
    for (int off = 16; off; off >>= 1) s += __shfl_xor_sync(0xffffffffu, s, off);
    if (lane == 0) cbn[k] = s;
}

// Fused final-argmin + gather + loss: one block per row.
__global__ void __launch_bounds__(256) vq_finish(const float* __restrict__ tv,
                                                 const int* __restrict__ ti,
                                                 const float* __restrict__ h,
                                                 const float* __restrict__ cb,
                                                 bf16* __restrict__ qdecb,
                                                 float* __restrict__ rowloss)
{
    int row = blockIdx.x, d = threadIdx.x;
    __shared__ int s_code;
    if (d < 32) {
        float v  = tv[row * 64 + d];      int i  = ti[row * 64 + d];
        float v2 = tv[row * 64 + 32 + d]; int i2 = ti[row * 64 + 32 + d];
        if (v2 < v || (v2 == v && i2 < i)) { v = v2; i = i2; }
        for (int off = 16; off; off >>= 1) {
            float ov = __shfl_xor_sync(0xffffffffu, v, off);
            int   oi = __shfl_xor_sync(0xffffffffu, i, off);
            if (ov < v || (ov == v && oi < i)) { v = ov; i = oi; }
        }
        if (d == 0) s_code = i;
    }
    __syncthreads();
    int code = s_code;
    float q = cb[(size_t)code * DMODEL + d];
    float hv = h[(size_t)row * DMODEL + d];
    qdecb[(size_t)row * DMODEL + d] = __float2bfloat16(q);
    float diff = q - hv;
    __shared__ float red[256];
    red[d] = diff * diff; __syncthreads();
    for (int s = 128; s; s >>= 1) { if (d < s) red[d] += red[d + s]; __syncthreads(); }
    if (d == 0) rowloss[row] = red[0];
}

__global__ void __launch_bounds__(256) finalize_loss(const float* __restrict__ rowloss,
                                                     float* __restrict__ out_loss)
{
    __shared__ float red[256];
    float s = 0.f;
    for (int i = threadIdx.x; i < ROWS; i += 256) s += rowloss[i];
    red[threadIdx.x] = s; __syncthreads();
    for (int st = 128; st; st >>= 1) { if (threadIdx.x < st) red[threadIdx.x] += red[threadIdx.x + st]; __syncthreads(); }
    if (threadIdx.x == 0) *out_loss = 1.25f * red[0] / (float)((size_t)ROWS * DMODEL);
}

// Final layer (Cin=64 NHWC bf16, Cout=3, 128->256, sigmoid)
__global__ void __launch_bounds__(256) convt_last(const bf16* __restrict__ in,
                                                  const float* __restrict__ w,
                                                  const float* __restrict__ bias,
                                                  float* __restrict__ out)
{
    __shared__ float ws[64 * 3 * 16];
    int tid = threadIdx.x;
    for (int i = tid; i < 64 * 3 * 16; i += 256) ws[i] = w[i];
    __syncthreads();
    int b = blockIdx.x;
    int oy = blockIdx.y * 16 + (tid >> 4);
    int ox = blockIdx.z * 16 + (tid & 15);
    int py = oy & 1, px = ox & 1;
    int jy = oy >> 1, jx = ox >> 1;
    int kys[2] = {3 - py, 1 - py};
    int kxs[2] = {3 - px, 1 - px};
    int iys[2] = {jy - 1 + py, jy + py};
    int ixs[2] = {jx - 1 + px, jx + px};
    float acc[3] = {bias[0], bias[1], bias[2]};
#pragma unroll
    for (int ty = 0; ty < 2; ty++) {
        int iy = iys[ty];
        if (iy < 0 || iy >= 128) continue;
#pragma unroll
        for (int tx = 0; tx < 2; tx++) {
            int ix = ixs[tx];
            if (ix < 0 || ix >= 128) continue;
            const bf16* p = in + ((size_t)(b * 128 + iy) * 128 + ix) * 64;
            int wo = kys[ty] * 4 + kxs[tx];
            for (int c8 = 0; c8 < 64; c8 += 8) {
                uint4 v = *(const uint4*)(p + c8);
                const bf16* e = (const bf16*)&v;
#pragma unroll
                for (int j = 0; j < 8; j++) {
                    float f = __bfloat162float(e[j]);
                    const float* wr = ws + (c8 + j) * 48 + wo;
                    acc[0] = fmaf(f, wr[0],  acc[0]);
                    acc[1] = fmaf(f, wr[16], acc[1]);
                    acc[2] = fmaf(f, wr[32], acc[2]);
                }
            }
        }
    }
#pragma unroll
    for (int co = 0; co < 3; co++)
        out[(((size_t)b * 3 + co) * 256 + oy) * 256 + ox] = 1.f / (1.f + __expf(-acc[co]));
}

// ---------------------------------------------------------------------------
// Host driver
// ---------------------------------------------------------------------------
#define SM128 (3*128*40*2 + 3*128*40*2 + 2048)
#define SM64  (3*128*40*2 + 3*64*40*2 + 2048)

extern "C" void kernel_launch(void* const* d_in, const int* in_sizes, int n_in,
                              void* d_out, int out_size)
{
    const float* x       = (const float*)d_in[0];
    const float* patch_w = (const float*)d_in[1];
    const float* patch_b = (const float*)d_in[2];
    const float* qkv_w   = (const float*)d_in[3];
    const float* qkv_b   = (const float*)d_in[4];
    const float* out_w   = (const float*)d_in[5];
    const float* out_b   = (const float*)d_in[6];
    const float* ln1_w   = (const float*)d_in[7];
    const float* ln1_b   = (const float*)d_in[8];
    const float* ln2_w   = (const float*)d_in[9];
    const float* ln2_b   = (const float*)d_in[10];
    const float* ff1_w   = (const float*)d_in[11];
    const float* ff1_b   = (const float*)d_in[12];
    const float* ff2_w   = (const float*)d_in[13];
    const float* ff2_b   = (const float*)d_in[14];
    const float* lnf_w   = (const float*)d_in[15];
    const float* lnf_b   = (const float*)d_in[16];
    const float* codebook= (const float*)d_in[17];
    const float* dec_w0  = (const float*)d_in[18];
    const float* dec_b0  = (const float*)d_in[19];
    const float* dec_w1  = (const float*)d_in[20];
    const float* dec_b1  = (const float*)d_in[21];
    const float* dec_w2  = (const float*)d_in[22];
    const float* dec_b2  = (const float*)d_in[23];
    const float* dec_w3  = (const float*)d_in[24];
    const float* dec_b3  = (const float*)d_in[25];

    float *h, *proj, *f2, *cbn, *tv, *rowloss;
    bf16 *xb, *pwb, *qkvwb, *outwb, *ff1wb, *ff2wb, *cbb, *wpb;
    bf16 *hb, *qkvb, *attnb, *midb, *qdecb, *y0b, *y1b, *y2b;
    int *ti;
    cudaGetSymbolAddress((void**)&h, g_h);
    cudaGetSymbolAddress((void**)&proj, g_proj);
    cudaGetSymbolAddress((void**)&f2, g_f2);
    cudaGetSymbolAddress((void**)&cbn, g_cbn);
    cudaGetSymbolAddress((void**)&tv, g_tv);
    cudaGetSymbolAddress((void**)&ti, g_ti);
    cudaGetSymbolAddress((void**)&rowloss, g_rowloss);
    cudaGetSymbolAddress((void**)&xb, g_xb);
    cudaGetSymbolAddress((void**)&pwb, g_pwb);
    cudaGetSymbolAddress((void**)&qkvwb, g_qkvwb);
    cudaGetSymbolAddress((void**)&outwb, g_outwb);
    cudaGetSymbolAddress((void**)&ff1wb, g_ff1wb);
    cudaGetSymbolAddress((void**)&ff2wb, g_ff2wb);
    cudaGetSymbolAddress((void**)&cbb, g_cbb);
    cudaGetSymbolAddress((void**)&wpb, g_wpb);
    cudaGetSymbolAddress((void**)&hb, g_hb);
    cudaGetSymbolAddress((void**)&qkvb, g_qkvb);
    cudaGetSymbolAddress((void**)&attnb, g_attnb);
    cudaGetSymbolAddress((void**)&midb, g_midb);
    cudaGetSymbolAddress((void**)&qdecb, g_qdecb);
    cudaGetSymbolAddress((void**)&y0b, g_y0b);
    cudaGetSymbolAddress((void**)&y1b, g_y1b);
    cudaGetSymbolAddress((void**)&y2b, g_y2b);

    cudaFuncSetAttribute(gemm_cp<1,3,64,3>,  cudaFuncAttributeMaxDynamicSharedMemorySize, SM64);
    cudaFuncSetAttribute(gemm_cp<5,0,64,3>,  cudaFuncAttributeMaxDynamicSharedMemorySize, SM64);
    cudaFuncSetAttribute(gemm_cp<1,0,64,3>,  cudaFuncAttributeMaxDynamicSharedMemorySize, SM64);
    cudaFuncSetAttribute(gemm_cp<2,0,64,3>,  cudaFuncAttributeMaxDynamicSharedMemorySize, SM64);
    cudaFuncSetAttribute(gemm_cp<3,0,128,2>, cudaFuncAttributeMaxDynamicSharedMemorySize, SM128);
    cudaFuncSetAttribute(gemm_cp<4,2,64,3>,  cudaFuncAttributeMaxDynamicSharedMemorySize, SM64);
    cudaFuncSetAttribute(attn_fused,         cudaFuncAttributeMaxDynamicSharedMemorySize, ATTN_SMEM);

    // ---- conversions + parity weights + cbn (independent, upfront) ----
    {
        CvtJobs j;
        j.s[0] = x;        j.d[0] = xb;    j.n[0] = (size_t)BATCH * 3 * IMG * IMG;
        j.s[1] = patch_w;  j.d[1] = pwb;   j.n[1] = (size_t)DMODEL * 3072;
        j.s[2] = qkv_w;    j.d[2] = qkvwb; j.n[2] = (size_t)LAYERS * 768 * 256;
        j.s[3] = out_w;    j.d[3] = outwb; j.n[3] = (size_t)LAYERS * 256 * 256;
        j.s[4] = ff1_w;    j.d[4] = ff1wb; j.n[4] = (size_t)LAYERS * 1024 * 256;
        j.s[5] = ff2_w;    j.d[5] = ff2wb; j.n[5] = (size_t)LAYERS * 256 * 1024;
        j.s[6] = codebook; j.d[6] = cbb;   j.n[6] = (size_t)KCODES * DMODEL;
        f2bf_multi<<<dim3(512, 7), 256>>>(j);
    }
    {
        WpJobs wj;
        wj.w[0] = dec_w0; wj.wp[0] = wpb + WP0; wj.cin[0] = 256; wj.cout[0] = 256;
        wj.w[1] = dec_w1; wj.wp[1] = wpb + WP1; wj.cin[1] = 256; wj.cout[1] = 128;
        wj.w[2] = dec_w2; wj.wp[2] = wpb + WP2; wj.cin[2] = 128; wj.cout[2] = 64;
        build_wp_multi<<<dim3(1024, 3), 256>>>(wj);
    }
    cbn_kernel<<<KCODES / 8, 256>>>(codebook, cbn);

    // ---- patch embedding ----
    gemm_cp<1, 3, 64, 3><<<dim3(4, 64), 256, SM64>>>(xb, pwb, patch_b, h, hb, nullptr,
                                                     ROWS, DMODEL, 3072, 0, 0);

    // ---- transformer ----
    for (int l = 0; l < LAYERS; l++) {
        gemm_cp<5, 0, 64, 3><<<dim3(12, 64), 256, SM64>>>(hb, qkvwb + (size_t)l * 768 * 256,
                 qkv_b + (size_t)l * 768, nullptr, qkvb, nullptr, ROWS, 768, 256, 0, 0);
        attn_fused<<<NPATCH, 256, ATTN_SMEM>>>(qkvb, attnb);
        gemm_cp<1, 0, 64, 3><<<dim3(4, 64), 256, SM64>>>(attnb, outwb + (size_t)l * 256 * 256,
                 out_b + (size_t)l * 256, proj, nullptr, nullptr, ROWS, 256, 256, 0, 0);
        ln_warp<<<ROWS / 8, 256>>>(h, proj, ln1_w + (size_t)l * 256, ln1_b + (size_t)l * 256, h, hb);
        gemm_cp<2, 0, 64, 3><<<dim3(16, 64), 256, SM64>>>(hb, ff1wb + (size_t)l * 1024 * 256,
                 ff1_b + (size_t)l * 1024, nullptr, midb, nullptr, ROWS, 1024, 256, 0, 0);
        gemm_cp<1, 0, 64, 3><<<dim3(4, 64), 256, SM64>>>(midb, ff2wb + (size_t)l * 256 * 1024,
                 ff2_b + (size_t)l * 256, f2, nullptr, nullptr, ROWS, 256, 1024, 0, 0);
        ln_warp<<<ROWS / 8, 256>>>(h, f2, ln2_w + (size_t)l * 256, ln2_b + (size_t)l * 256, h, hb);
    }
    ln_warp<<<ROWS / 8, 256>>>(h, nullptr, lnf_w, lnf_b, h, hb);

    // ---- VQ ----
    gemm_cp<3, 0, 128, 2><<<dim3(64, 64), 256, SM128>>>(hb, cbb, cbn, tv, nullptr, ti,
                                                        ROWS, KCODES, 256, 0, 0);
    vq_finish<<<ROWS, 256>>>(tv, ti, h, codebook, qdecb, rowloss);

    // ---- decoder: 4-parity-fused NHWC implicit-im2col GEMMs (BN=64, 3 CTA/SM) ----
    gemm_cp<4, 2, 64, 3><<<dim3(4, 64, 4), 256, SM64>>>(qdecb, wpb + WP0, dec_b0,
            nullptr, y0b, nullptr, 8192, 256, 1024, 4, 8);
    gemm_cp<4, 2, 64, 3><<<dim3(2, 256, 4), 256, SM64>>>(y0b, wpb + WP1, dec_b1,
            nullptr, y1b, nullptr, 32768, 128, 1024, 5, 8);
    gemm_cp<4, 2, 64, 3><<<dim3(1, 1024, 4), 256, SM64>>>(y1b, wpb + WP2, dec_b2,
            nullptr, y2b, nullptr, 131072, 64, 512, 6, 7);

    // ---- final conv_t + sigmoid -> x_hat ----
    convt_last<<<dim3(BATCH, 16, 16), 256>>>(y2b, dec_w3, dec_b3, (float*)d_out);

    // ---- vq_loss scalar ----
    if (out_size > NXHAT)
        finalize_loss<<<1, 256>>>(rowloss, (float*)d_out + (out_size - 1));
}

// round 16
// speedup vs baseline: 1.0183x; 1.0183x over previous
#include <cuda_runtime.h>
#include <cuda_bf16.h>
#include <math.h>
#include <stdint.h>

typedef __nv_bfloat16 bf16;

#define IMG 512
#define CIN_ 3
#define DMODEL 256
#define KCODES 8192
#define LAYERS 6
#define HEADS 8
#define FFDIM 1024
#define BATCH 32
#define NPATCH 256
#define ROWS 8192
#define NXHAT (BATCH * 3 * 256 * 256)

// ---------------------------------------------------------------------------
// Static scratch
// ---------------------------------------------------------------------------
__device__ float g_h[ROWS * DMODEL];
__device__ float g_proj[ROWS * DMODEL];
__device__ float g_f2[ROWS * DMODEL];
__device__ float g_cbn[KCODES];
__device__ float g_tv[ROWS * 64];
__device__ int   g_ti[ROWS * 64];
__device__ float g_rowloss[ROWS];

__device__ bf16 g_xb[BATCH * 3 * IMG * IMG];
__device__ bf16 g_pwb[DMODEL * 3072];
__device__ bf16 g_qkvwb[LAYERS * 768 * 256];
__device__ bf16 g_outwb[LAYERS * 256 * 256];
__device__ bf16 g_ff1wb[LAYERS * 1024 * 256];
__device__ bf16 g_ff2wb[LAYERS * 256 * 1024];
__device__ bf16 g_cbb[KCODES * DMODEL];
__device__ bf16 g_wpb[1703936];                 // parity weights, 3 layers
__device__ bf16 g_hb[ROWS * DMODEL];
__device__ bf16 g_qkvb[ROWS * 768];
__device__ bf16 g_attnb[ROWS * DMODEL];
__device__ bf16 g_midb[ROWS * FFDIM];
__device__ bf16 g_qdecb[ROWS * DMODEL];         // NHWC (b,16,16,256)
__device__ bf16 g_y0b[BATCH * 32 * 32 * 256];   // NHWC
__device__ bf16 g_y1b[BATCH * 64 * 64 * 128];   // NHWC
__device__ bf16 g_y2b[BATCH * 128 * 128 * 64];  // NHWC

#define WP0 0
#define WP1 1048576
#define WP2 1572864

// ---------------------------------------------------------------------------
// Helpers
// ---------------------------------------------------------------------------
__device__ __forceinline__ float gelu_exact(float v) {
    return 0.5f * v * (1.0f + erff(v * 0.7071067811865476f));
}
__device__ __forceinline__ uint32_t b2pack(float x, float y) {
    __nv_bfloat162 h = __floats2bfloat162_rn(x, y);
    return *reinterpret_cast<uint32_t*>(&h);
}
__device__ __forceinline__ uint32_t smem_u32(const void* p) {
    uint32_t r;
    asm("{ .reg .u64 t; cvta.to.shared.u64 t, %1; cvt.u32.u64 %0, t; }"
        : "=r"(r) : "l"(p));
    return r;
}
__device__ __forceinline__ void ldm_x4(uint32_t& r0, uint32_t& r1, uint32_t& r2,
                                       uint32_t& r3, uint32_t addr) {
    asm volatile("ldmatrix.sync.aligned.m8n8.x4.shared.b16 {%0,%1,%2,%3}, [%4];"
                 : "=r"(r0), "=r"(r1), "=r"(r2), "=r"(r3) : "r"(addr));
}
__device__ __forceinline__ void mma16816(float* c, const uint32_t* a,
                                         uint32_t b0, uint32_t b1) {
    asm volatile(
        "mma.sync.aligned.m16n8k16.row.col.f32.bf16.bf16.f32 "
        "{%0,%1,%2,%3},{%4,%5,%6,%7},{%8,%9},{%0,%1,%2,%3};"
        : "+f"(c[0]), "+f"(c[1]), "+f"(c[2]), "+f"(c[3])
        : "r"(a[0]), "r"(a[1]), "r"(a[2]), "r"(a[3]), "r"(b0), "r"(b1));
}
__device__ __forceinline__ void cpa16(uint32_t dst, const void* src, int sz) {
    asm volatile("cp.async.cg.shared.global [%0], [%1], 16, %2;"
                 :: "r"(dst), "l"(src), "r"(sz) : "memory");
}
__device__ __forceinline__ void cp_commit() {
    asm volatile("cp.async.commit_group;" ::: "memory");
}
template<int W> __device__ __forceinline__ void cp_wait() {
    asm volatile("cp.async.wait_group %0;" :: "n"(W) : "memory");
}

// ---------------------------------------------------------------------------
// bf16 cp.async 3-stage tensor-core GEMM (K-chunk 32, pitch 40).
//   C[M,N] = A @ B^T
//   AMODE 0: A bf16 row-major M x K.
//   AMODE 2: implicit conv_t im2col over NHWC bf16 (Cin=2^cinlg, Hin=2^hinlg);
//            parity = blockIdx.z; B offset by parity internally.
//   AMODE 3: implicit patch im2col over bf16 x (B,3,512,512).
// EPI: 1 +bias fp32 C (+bf16 Cb if non-null) | 2 +bias+GELU bf16 | 5 +bias bf16 |
//      3 VQ argmin | 4 +bias+ReLU scatter to bf16 NHWC at parity offset.
// MB: min blocks per SM (3 for BN=64, 2 for BN=128).
// ---------------------------------------------------------------------------
template<int EPI, int AMODE, int BN_, int MB>
__global__ void __launch_bounds__(256, MB) gemm_cp(
    const bf16* __restrict__ A, const bf16* __restrict__ B,
    const float* __restrict__ bias, float* __restrict__ C,
    bf16* __restrict__ Cb, int* __restrict__ Ci,
    int M, int N, int K, int hinlg, int cinlg)
{
    constexpr int NT = BN_ / 16;
    extern __shared__ __align__(16) char dynsmem[];
    bf16* Asp = (bf16*)dynsmem;                 // [3][128][40]
    bf16* Bsp = Asp + 3 * 128 * 40;             // [3][BN_][40]
    float* s_val = (float*)(Bsp + 3 * BN_ * 40);
    int*   s_idx = (int*)(s_val + 256);

    const int tid  = threadIdx.x;
    const int lane = tid & 31, warp = tid >> 5;
    const int wm = warp >> 1, wn = warp & 1;
    const int g = lane >> 2, tig = lane & 3;
    const int row0 = blockIdx.y * 128;
    const int col0 = blockIdx.x * BN_;
    const int m_off = wm * 32;
    const int n_off = wn * (BN_ / 2);
    const int pyx = (AMODE == 2) ? blockIdx.z : 0;
    if constexpr (AMODE == 2) B += (size_t)pyx * N * K;

    const uint32_t as_base = smem_u32(Asp);
    const uint32_t bs_base = smem_u32(Bsp);
    const int a_ld_row = lane & 15;
    const int a_ld_col = (lane >> 4) * 8;
    const int b_ld_row = (lane & 7) + ((lane & 16) ? 8 : 0);
    const int b_ld_col = (lane & 8) ? 8 : 0;

    const int cp_m = tid >> 1;
    const int cp_c = (tid & 1) * 16;

    int am_b = 0, am_jy = 0, am_jx = 0, Hin = 0;
    if constexpr (AMODE == 2) {
        Hin = 1 << hinlg;
        int m = row0 + cp_m;
        am_b = m >> (2 * hinlg);
        int rem = m & ((1 << (2 * hinlg)) - 1);
        am_jy = rem >> hinlg;
        am_jx = rem & (Hin - 1);
    } else if constexpr (AMODE == 3) {
        int m = row0 + cp_m;
        am_b = m >> 8;
        int n = m & 255;
        am_jy = n >> 4;
        am_jx = n & 15;
    }

    float acc[2][NT][4];
#pragma unroll
    for (int i = 0; i < 2; i++)
#pragma unroll
        for (int j = 0; j < NT; j++)
#pragma unroll
            for (int k = 0; k < 4; k++) acc[i][j][k] = 0.f;

    auto copyTile = [&](int buf, int t) {
        const int k0 = t * 32;
        uint32_t adst = as_base + ((uint32_t)(buf * 128 + cp_m) * 40 + cp_c) * 2;
        if constexpr (AMODE == 0) {
            const bf16* s = A + (size_t)(row0 + cp_m) * K + k0 + cp_c;
            cpa16(adst, s, 16);
            cpa16(adst + 16, s + 8, 16);
        } else if constexpr (AMODE == 3) {
            int c  = k0 >> 10;
            int py = (k0 & 1023) >> 5;
            const bf16* s = A + (((size_t)(am_b * 3 + c) * IMG + am_jy * 32 + py) * IMG
                                 + am_jx * 32 + cp_c);
            cpa16(adst, s, 16);
            cpa16(adst + 16, s + 8, 16);
        } else {
            int dd = k0 >> cinlg;
            int ci0 = (k0 & ((1 << cinlg) - 1)) + cp_c;
            int dy = dd >> 1, dx = dd & 1;
            int iy = am_jy - 1 + (pyx >> 1) + dy;
            int ix = am_jx - 1 + (pyx & 1) + dx;
            bool ok = (iy >= 0) & (iy < Hin) & (ix >= 0) & (ix < Hin);
            const bf16* s = ok ? (A + ((((size_t)am_b << hinlg) + iy << hinlg) + ix << cinlg) + ci0)
                               : A;
            int sz = ok ? 16 : 0;
            cpa16(adst, s, sz);
            cpa16(adst + 16, ok ? (s + 8) : s, sz);
        }
        if constexpr (BN_ == 128) {
            uint32_t bdst = bs_base + ((uint32_t)(buf * BN_ + cp_m) * 40 + cp_c) * 2;
            const bf16* s = B + (size_t)(col0 + cp_m) * K + k0 + cp_c;
            cpa16(bdst, s, 16);
            cpa16(bdst + 16, s + 8, 16);
        } else {
            uint32_t bdst = bs_base + ((uint32_t)(buf * BN_ + (tid >> 2)) * 40 + (tid & 3) * 8) * 2;
            const bf16* s = B + (size_t)(col0 + (tid >> 2)) * K + k0 + (tid & 3) * 8;
            cpa16(bdst, s, 16);
        }
    };

    const int nk = K >> 5;
    copyTile(0, 0); cp_commit();
    copyTile(1, 1); cp_commit();

    int cur = 0, wr = 2;
    for (int t = 0; t < nk; t++) {
        cp_wait<1>();
        __syncthreads();
        if (t + 2 < nk) copyTile(wr, t + 2);
        cp_commit();
#pragma unroll
        for (int ks = 0; ks < 2; ks++) {
            uint32_t af[2][4];
#pragma unroll
            for (int mt = 0; mt < 2; mt++) {
                uint32_t addr = as_base +
                    ((uint32_t)(cur * 128 + m_off + mt * 16 + a_ld_row) * 40 +
                     (uint32_t)(ks * 16 + a_ld_col)) * 2;
                ldm_x4(af[mt][0], af[mt][1], af[mt][2], af[mt][3], addr);
            }
#pragma unroll
            for (int p = 0; p < NT / 2; p++) {
                uint32_t b0, b1, b2, b3;
                uint32_t addr = bs_base +
                    ((uint32_t)(cur * BN_ + n_off + p * 16 + b_ld_row) * 40 +
                     (uint32_t)(ks * 16 + b_ld_col)) * 2;
                ldm_x4(b0, b1, b2, b3, addr);
#pragma unroll
                for (int mt = 0; mt < 2; mt++) {
                    mma16816(acc[mt][2 * p],     af[mt], b0, b1);
                    mma16816(acc[mt][2 * p + 1], af[mt], b2, b3);
                }
            }
        }
        cur = (cur == 2) ? 0 : cur + 1;
        wr  = (wr == 2) ? 0 : wr + 1;
    }

    if constexpr (EPI == 1 || EPI == 2 || EPI == 5) {
#pragma unroll
        for (int mt = 0; mt < 2; mt++)
#pragma unroll
            for (int nt = 0; nt < NT; nt++) {
                int cc = col0 + n_off + nt * 8 + tig * 2;
                float b0v = bias[cc], b1v = bias[cc + 1];
#pragma unroll
                for (int half = 0; half < 2; half++) {
                    int rr = row0 + m_off + mt * 16 + g + half * 8;
                    float v0 = acc[mt][nt][half * 2 + 0] + b0v;
                    float v1 = acc[mt][nt][half * 2 + 1] + b1v;
                    if constexpr (EPI == 2) {
                        v0 = gelu_exact(v0); v1 = gelu_exact(v1);
                        *(uint32_t*)&Cb[(size_t)rr * N + cc] = b2pack(v0, v1);
                    } else if constexpr (EPI == 5) {
                        *(uint32_t*)&Cb[(size_t)rr * N + cc] = b2pack(v0, v1);
                    } else {
                        float2 o; o.x = v0; o.y = v1;
                        *(float2*)&C[(size_t)rr * N + cc] = o;
                        if (Cb)
                            *(uint32_t*)&Cb[(size_t)rr * N + cc] = b2pack(v0, v1);
                    }
                }
            }
    } else if constexpr (EPI == 4) {
        const int Hi = 1 << hinlg, Hout = 2 << hinlg;
        const int py = pyx >> 1, px = pyx & 1;
#pragma unroll
        for (int mt = 0; mt < 2; mt++)
#pragma unroll
            for (int half = 0; half < 2; half++) {
                int rr = row0 + m_off + mt * 16 + g + half * 8;
                int b = rr >> (2 * hinlg);
                int rem = rr & ((1 << (2 * hinlg)) - 1);
                int jy = rem >> hinlg, jx = rem & (Hi - 1);
                bf16* orow = Cb + ((size_t)((b * Hout + 2 * jy + py) * Hout + 2 * jx + px)) * N;
#pragma unroll
                for (int nt = 0; nt < NT; nt++) {
                    int cc = col0 + n_off + nt * 8 + tig * 2;
                    float v0 = fmaxf(acc[mt][nt][half * 2 + 0] + bias[cc], 0.f);
                    float v1 = fmaxf(acc[mt][nt][half * 2 + 1] + bias[cc + 1], 0.f);
                    *(uint32_t*)&orow[cc] = b2pack(v0, v1);
                }
            }
    } else { // EPI 3
        float bv[4]; int bi[4];
#pragma unroll
        for (int r = 0; r < 4; r++) { bv[r] = 3.4e38f; bi[r] = 0; }
#pragma unroll
        for (int mt = 0; mt < 2; mt++)
#pragma unroll
            for (int half = 0; half < 2; half++) {
                int r = mt * 2 + half;
#pragma unroll
                for (int nt = 0; nt < NT; nt++)
#pragma unroll
                    for (int q = 0; q < 2; q++) {
                        int cc = col0 + n_off + nt * 8 + tig * 2 + q;
                        float v = bias[cc] - 2.f * acc[mt][nt][half * 2 + q];
                        if (v < bv[r] || (v == bv[r] && cc < bi[r])) { bv[r] = v; bi[r] = cc; }
                    }
            }
#pragma unroll
        for (int off = 1; off <= 2; off <<= 1)
#pragma unroll
            for (int r = 0; r < 4; r++) {
                float ov = __shfl_xor_sync(0xffffffffu, bv[r], off);
                int   oi = __shfl_xor_sync(0xffffffffu, bi[r], off);
                if (ov < bv[r] || (ov == bv[r] && oi < bi[r])) { bv[r] = ov; bi[r] = oi; }
            }
        if (tig == 0) {
#pragma unroll
            for (int r = 0; r < 4; r++) {
                int sr = m_off + (r >> 1) * 16 + g + (r & 1) * 8;
                s_val[wn * 128 + sr] = bv[r];
                s_idx[wn * 128 + sr] = bi[r];
            }
        }
        __syncthreads();
        if (tid < 128) {
            float v0 = s_val[tid], v1 = s_val[128 + tid];
            int   i0 = s_idx[tid], i1 = s_idx[128 + tid];
            if (v1 < v0 || (v1 == v0 && i1 < i0)) { v0 = v1; i0 = i1; }
            C [(size_t)(row0 + tid) * gridDim.x + blockIdx.x] = v0;
            Ci[(size_t)(row0 + tid) * gridDim.x + blockIdx.x] = i0;
        }
    }
}

// ---------------------------------------------------------------------------
// Batched fp32 -> bf16 convert: gridDim.y selects the job.
// ---------------------------------------------------------------------------
struct CvtJobs {
    const float* s[7];
    bf16* d[7];
    size_t n[7];
};
__global__ void f2bf_multi(CvtJobs j)
{
    const float* __restrict__ src = j.s[blockIdx.y];
    bf16* __restrict__ dst = j.d[blockIdx.y];
    size_t n = j.n[blockIdx.y];
    for (size_t i = ((size_t)blockIdx.x * blockDim.x + threadIdx.x) * 4; i < n;
         i += (size_t)gridDim.x * blockDim.x * 4) {
        float4 v = *(const float4*)(src + i);
        uint2 p;
        p.x = b2pack(v.x, v.y);
        p.y = b2pack(v.z, v.w);
        *(uint2*)(dst + i) = p;
    }
}

// ---------------------------------------------------------------------------
// Batched parity-weight build: gridDim.y selects the decoder layer.
// ---------------------------------------------------------------------------
struct WpJobs {
    const float* w[3];
    bf16* wp[3];
    int cin[3], cout[3];
};
__global__ void build_wp_multi(WpJobs j)
{
    const float* __restrict__ w = j.w[blockIdx.y];
    bf16* __restrict__ wp = j.wp[blockIdx.y];
    int Cin = j.cin[blockIdx.y], Cout = j.cout[blockIdx.y];
    int total = 16 * Cin * Cout;
    for (int i = blockIdx.x * blockDim.x + threadIdx.x; i < total; i += gridDim.x * blockDim.x) {
        int ci = i % Cin;
        int rest = i / Cin;
        int dd = rest & 3;
        int co = (rest >> 2) % Cout;
        int p = (rest >> 2) / Cout;
        int dy = dd >> 1, dx = dd & 1;
        int py = p >> 1, px = p & 1;
        int ky = dy ? (1 - py) : (3 - py);
        int kx = dx ? (1 - px) : (3 - px);
        wp[i] = __float2bfloat16(w[(((size_t)ci * Cout + co) * 4 + ky) * 4 + kx]);
    }
}

// ---------------------------------------------------------------------------
// Fused attention: one block per patch bt, warp = head, warp-private smem.
// K/V stored bf16 in smem (lossless: sourced from bf16 gmem); Q and S fp32.
// Per-warp: Q 4224 + Kb 2112 + Vb 2112 + S 4224 = 12672 B; x8 warps = 101376 B
// -> 2 CTAs/SM (vs 1 before).
// ---------------------------------------------------------------------------
__global__ void __launch_bounds__(256) attn_fused(const bf16* __restrict__ qkv,
                                                  bf16* __restrict__ o)
{
    extern __shared__ __align__(16) char asmem_raw[];
    const int bt = blockIdx.x;
    const int w = threadIdx.x >> 5, lane = threadIdx.x & 31;
    char* wb = asmem_raw + w * 12672;
    float* Q = (float*)wb;                    // [32][33] fp32
    bf16* Kb = (bf16*)(wb + 4224);            // [32][33] bf16
    bf16* Vb = (bf16*)(wb + 4224 + 2112);     // [32][33] bf16
    float* S = (float*)(wb + 4224 + 2112 + 2112); // [32][33] fp32

#pragma unroll
    for (int s = 0; s < 32; s++) {
        size_t base = ((size_t)s * NPATCH + bt) * 768 + w * 32 + lane;
        Q[s * 33 + lane]  = __bfloat162float(qkv[base]);
        Kb[s * 33 + lane] = qkv[base + 256];
        Vb[s * 33 + lane] = qkv[base + 512];
    }
    __syncwarp();
    {
        float Kr[32];
#pragma unroll
        for (int d = 0; d < 32; d++) Kr[d] = __bfloat162float(Kb[lane * 33 + d]);
#pragma unroll
        for (int s = 0; s < 32; s++) {
            float acc = 0.f;
#pragma unroll
            for (int d = 0; d < 32; d++) acc = fmaf(Q[s * 33 + d], Kr[d], acc);
            S[s * 33 + lane] = acc * 0.17677669529663687f;
        }
    }
    __syncwarp();
    {
        float row[32];
        float m = -3.4e38f;
#pragma unroll
        for (int t = 0; t < 32; t++) { row[t] = S[lane * 33 + t]; m = fmaxf(m, row[t]); }
        float sum = 0.f;
#pragma unroll
        for (int t = 0; t < 32; t++) { row[t] = __expf(row[t] - m); sum += row[t]; }
        float inv = 1.f / sum;
#pragma unroll
        for (int t = 0; t < 32; t++) S[lane * 33 + t] = row[t] * inv;
    }
    __syncwarp();
    {
        float Vr[32];
#pragma unroll
        for (int t = 0; t < 32; t++) Vr[t] = __bfloat162float(Vb[t * 33 + lane]);
#pragma unroll
        for (int s = 0; s < 32; s++) {
            float acc = 0.f;
#pragma unroll
            for (int t = 0; t < 32; t++) acc = fmaf(S[s * 33 + t], Vr[t], acc);
            o[((size_t)s * NPATCH + bt) * DMODEL + w * 32 + lane] = __float2bfloat16(acc);
        }
    }
}
#define ATTN_SMEM 101376

// ---------------------------------------------------------------------------
// Warp-per-row LayerNorm over D=256; dual fp32 + bf16 output.
// ---------------------------------------------------------------------------
__global__ void __launch_bounds__(256) ln_warp(const float* __restrict__ x,
                                               const float* __restrict__ r,
                                               const float* __restrict__ g,
                                               const float* __restrict__ b,
                                               float* __restrict__ out,
                                               bf16* __restrict__ outb)
{
    int lane = threadIdx.x & 31;
    int row = blockIdx.x * 8 + (threadIdx.x >> 5);
    const float* xr = x + (size_t)row * DMODEL;
    int d0 = lane * 4, d1 = 128 + lane * 4;
    float4 v0 = *(const float4*)(xr + d0);
    float4 v1 = *(const float4*)(xr + d1);
    if (r) {
        const float* rr = r + (size_t)row * DMODEL;
        float4 a0 = *(const float4*)(rr + d0);
        float4 a1 = *(const float4*)(rr + d1);
        v0.x += a0.x; v0.y += a0.y; v0.z += a0.z; v0.w += a0.w;
        v1.x += a1.x; v1.y += a1.y; v1.z += a1.z; v1.w += a1.w;
    }
    float s = v0.x + v0.y + v0.z + v0.w + v1.x + v1.y + v1.z + v1.w;
#pragma unroll
    for (int off = 16; off; off >>= 1) s += __shfl_xor_sync(0xffffffffu, s, off);
    float mean = s * (1.f / DMODEL);
    float c0x = v0.x - mean, c0y = v0.y - mean, c0z = v0.z - mean, c0w = v0.w - mean;
    float c1x = v1.x - mean, c1y = v1.y - mean, c1z = v1.z - mean, c1w = v1.w - mean;
    float ss = c0x*c0x + c0y*c0y + c0z*c0z + c0w*c0w
             + c1x*c1x + c1y*c1y + c1z*c1z + c1w*c1w;
#pragma unroll
    for (int off = 16; off; off >>= 1) ss += __shfl_xor_sync(0xffffffffu, ss, off);
    float inv = rsqrtf(ss * (1.f / DMODEL) + 1e-5f);
    float4 g0 = *(const float4*)(g + d0), g1 = *(const float4*)(g + d1);
    float4 b0 = *(const float4*)(b + d0), b1 = *(const float4*)(b + d1);
    float4 o0, o1;
    o0.x = c0x * inv * g0.x + b0.x; o0.y = c0y * inv * g0.y + b0.y;
    o0.z = c0z * inv * g0.z + b0.z; o0.w = c0w * inv * g0.w + b0.w;
    o1.x = c1x * inv * g1.x + b1.x; o1.y = c1y * inv * g1.y + b1.y;
    o1.z = c1z * inv * g1.z + b1.z; o1.w = c1w * inv * g1.w + b1.w;
    float* orow = out + (size_t)row * DMODEL;
    *(float4*)(orow + d0) = o0;
    *(float4*)(orow + d1) = o1;
    if (outb) {
        bf16* obr = outb + (size_t)row * DMODEL;
        uint2 p0, p1;
        p0.x = b2pack(o0.x, o0.y); p0.y = b2pack(o0.z, o0.w);
        p1.x = b2pack(o1.x, o1.y); p1.y = b2pack(o1.z, o1.w);
        *(uint2*)(obr + d0) = p0;
        *(uint2*)(obr + d1) = p1;
    }
}

// ---------------------------------------------------------------------------
// VQ helpers
// ---------------------------------------------------------------------------
__global__ void __launch_bounds__(256) cbn_kernel(const float* __restrict__ cb,
                                                  float* __restrict__ cbn)
{
    int lane = threadIdx.x & 31;
    int k = blockIdx.x * 8 + (threadIdx.x >> 5);
    const float* row = cb + (size_t)k * DMODEL;
    float s = 0.f;
#pragma unroll
    for (int i = 0; i < 2; i++) {
        float4 v = *(const float4*)(row + lane * 4 + i * 128);
        s += v.x * v.x + v.y * v.y + v.z * v.z + v.w * v.w;
    }
#pragma unroll
    for (int off = 16; off; off >>= 1) s += __shfl_xor_sync(0xffffffffu, s, off);
    if (lane == 0) cbn[k] = s;
}

// Fused final-argmin + gather + loss: one block per row.
__global__ void __launch_bounds__(256) vq_finish(const float* __restrict__ tv,
                                                 const int* __restrict__ ti,
                                                 const float* __restrict__ h,
                                                 const float* __restrict__ cb,
                                                 bf16* __restrict__ qdecb,
                                                 float* __restrict__ rowloss)
{
    int row = blockIdx.x, d = threadIdx.x;
    __shared__ int s_code;
    if (d < 32) {
        float v  = tv[row * 64 + d];      int i  = ti[row * 64 + d];
        float v2 = tv[row * 64 + 32 + d]; int i2 = ti[row * 64 + 32 + d];
        if (v2 < v || (v2 == v && i2 < i)) { v = v2; i = i2; }
        for (int off = 16; off; off >>= 1) {
            float ov = __shfl_xor_sync(0xffffffffu, v, off);
            int   oi = __shfl_xor_sync(0xffffffffu, i, off);
            if (ov < v || (ov == v && oi < i)) { v = ov; i = oi; }
        }
        if (d == 0) s_code = i;
    }
    __syncthreads();
    int code = s_code;
    float q = cb[(size_t)code * DMODEL + d];
    float hv = h[(size_t)row * DMODEL + d];
    qdecb[(size_t)row * DMODEL + d] = __float2bfloat16(q);
    float diff = q - hv;
    __shared__ float red[256];
    red[d] = diff * diff; __syncthreads();
    for (int s = 128; s; s >>= 1) { if (d < s) red[d] += red[d + s]; __syncthreads(); }
    if (d == 0) rowloss[row] = red[0];
}

__global__ void __launch_bounds__(256) finalize_loss(const float* __restrict__ rowloss,
                                                     float* __restrict__ out_loss)
{
    __shared__ float red[256];
    float s = 0.f;
    for (int i = threadIdx.x; i < ROWS; i += 256) s += rowloss[i];
    red[threadIdx.x] = s; __syncthreads();
    for (int st = 128; st; st >>= 1) { if (threadIdx.x < st) red[threadIdx.x] += red[threadIdx.x + st]; __syncthreads(); }
    if (threadIdx.x == 0) *out_loss = 1.25f * red[0] / (float)((size_t)ROWS * DMODEL);
}

// Final layer (Cin=64 NHWC bf16, Cout=3, 128->256, sigmoid)
__global__ void __launch_bounds__(256) convt_last(const bf16* __restrict__ in,
                                                  const float* __restrict__ w,
                                                  const float* __restrict__ bias,
                                                  float* __restrict__ out)
{
    __shared__ float ws[64 * 3 * 16];
    int tid = threadIdx.x;
    for (int i = tid; i < 64 * 3 * 16; i += 256) ws[i] = w[i];
    __syncthreads();
    int b = blockIdx.x;
    int oy = blockIdx.y * 16 + (tid >> 4);
    int ox = blockIdx.z * 16 + (tid & 15);
    int py = oy & 1, px = ox & 1;
    int jy = oy >> 1, jx = ox >> 1;
    int kys[2] = {3 - py, 1 - py};
    int kxs[2] = {3 - px, 1 - px};
    int iys[2] = {jy - 1 + py, jy + py};
    int ixs[2] = {jx - 1 + px, jx + px};
    float acc[3] = {bias[0], bias[1], bias[2]};
#pragma unroll
    for (int ty = 0; ty < 2; ty++) {
        int iy = iys[ty];
        if (iy < 0 || iy >= 128) continue;
#pragma unroll
        for (int tx = 0; tx < 2; tx++) {
            int ix = ixs[tx];
            if (ix < 0 || ix >= 128) continue;
            const bf16* p = in + ((size_t)(b * 128 + iy) * 128 + ix) * 64;
            int wo = kys[ty] * 4 + kxs[tx];
            for (int c8 = 0; c8 < 64; c8 += 8) {
                uint4 v = *(const uint4*)(p + c8);
                const bf16* e = (const bf16*)&v;
#pragma unroll
                for (int j = 0; j < 8; j++) {
                    float f = __bfloat162float(e[j]);
                    const float* wr = ws + (c8 + j) * 48 + wo;
                    acc[0] = fmaf(f, wr[0],  acc[0]);
                    acc[1] = fmaf(f, wr[16], acc[1]);
                    acc[2] = fmaf(f, wr[32], acc[2]);
                }
            }
        }
    }
#pragma unroll
    for (int co = 0; co < 3; co++)
        out[(((size_t)b * 3 + co) * 256 + oy) * 256 + ox] = 1.f / (1.f + __expf(-acc[co]));
}

// ---------------------------------------------------------------------------
// Host driver (round-12 proven launch config + bf16-KV attention)
// ---------------------------------------------------------------------------
#define SM128 (3*128*40*2 + 3*128*40*2 + 2048)
#define SM64  (3*128*40*2 + 3*64*40*2 + 2048)

extern "C" void kernel_launch(void* const* d_in, const int* in_sizes, int n_in,
                              void* d_out, int out_size)
{
    const float* x       = (const float*)d_in[0];
    const float* patch_w = (const float*)d_in[1];
    const float* patch_b = (const float*)d_in[2];
    const float* qkv_w   = (const float*)d_in[3];
    const float* qkv_b   = (const float*)d_in[4];
    const float* out_w   = (const float*)d_in[5];
    const float* out_b   = (const float*)d_in[6];
    const float* ln1_w   = (const float*)d_in[7];
    const float* ln1_b   = (const float*)d_in[8];
    const float* ln2_w   = (const float*)d_in[9];
    const float* ln2_b   = (const float*)d_in[10];
    const float* ff1_w   = (const float*)d_in[11];
    const float* ff1_b   = (const float*)d_in[12];
    const float* ff2_w   = (const float*)d_in[13];
    const float* ff2_b   = (const float*)d_in[14];
    const float* lnf_w   = (const float*)d_in[15];
    const float* lnf_b   = (const float*)d_in[16];
    const float* codebook= (const float*)d_in[17];
    const float* dec_w0  = (const float*)d_in[18];
    const float* dec_b0  = (const float*)d_in[19];
    const float* dec_w1  = (const float*)d_in[20];
    const float* dec_b1  = (const float*)d_in[21];
    const float* dec_w2  = (const float*)d_in[22];
    const float* dec_b2  = (const float*)d_in[23];
    const float* dec_w3  = (const float*)d_in[24];
    const float* dec_b3  = (const float*)d_in[25];

    float *h, *proj, *f2, *cbn, *tv, *rowloss;
    bf16 *xb, *pwb, *qkvwb, *outwb, *ff1wb, *ff2wb, *cbb, *wpb;
    bf16 *hb, *qkvb, *attnb, *midb, *qdecb, *y0b, *y1b, *y2b;
    int *ti;
    cudaGetSymbolAddress((void**)&h, g_h);
    cudaGetSymbolAddress((void**)&proj, g_proj);
    cudaGetSymbolAddress((void**)&f2, g_f2);
    cudaGetSymbolAddress((void**)&cbn, g_cbn);
    cudaGetSymbolAddress((void**)&tv, g_tv);
    cudaGetSymbolAddress((void**)&ti, g_ti);
    cudaGetSymbolAddress((void**)&rowloss, g_rowloss);
    cudaGetSymbolAddress((void**)&xb, g_xb);
    cudaGetSymbolAddress((void**)&pwb, g_pwb);
    cudaGetSymbolAddress((void**)&qkvwb, g_qkvwb);
    cudaGetSymbolAddress((void**)&outwb, g_outwb);
    cudaGetSymbolAddress((void**)&ff1wb, g_ff1wb);
    cudaGetSymbolAddress((void**)&ff2wb, g_ff2wb);
    cudaGetSymbolAddress((void**)&cbb, g_cbb);
    cudaGetSymbolAddress((void**)&wpb, g_wpb);
    cudaGetSymbolAddress((void**)&hb, g_hb);
    cudaGetSymbolAddress((void**)&qkvb, g_qkvb);
    cudaGetSymbolAddress((void**)&attnb, g_attnb);
    cudaGetSymbolAddress((void**)&midb, g_midb);
    cudaGetSymbolAddress((void**)&qdecb, g_qdecb);
    cudaGetSymbolAddress((void**)&y0b, g_y0b);
    cudaGetSymbolAddress((void**)&y1b, g_y1b);
    cudaGetSymbolAddress((void**)&y2b, g_y2b);

    cudaFuncSetAttribute(gemm_cp<1,3,64,3>,  cudaFuncAttributeMaxDynamicSharedMemorySize, SM64);
    cudaFuncSetAttribute(gemm_cp<5,0,128,2>, cudaFuncAttributeMaxDynamicSharedMemorySize, SM128);
    cudaFuncSetAttribute(gemm_cp<1,0,64,3>,  cudaFuncAttributeMaxDynamicSharedMemorySize, SM64);
    cudaFuncSetAttribute(gemm_cp<2,0,128,2>, cudaFuncAttributeMaxDynamicSharedMemorySize, SM128);
    cudaFuncSetAttribute(gemm_cp<3,0,128,2>, cudaFuncAttributeMaxDynamicSharedMemorySize, SM128);
    cudaFuncSetAttribute(gemm_cp<4,2,128,2>, cudaFuncAttributeMaxDynamicSharedMemorySize, SM128);
    cudaFuncSetAttribute(gemm_cp<4,2,64,3>,  cudaFuncAttributeMaxDynamicSharedMemorySize, SM64);
    cudaFuncSetAttribute(attn_fused,         cudaFuncAttributeMaxDynamicSharedMemorySize, ATTN_SMEM);

    // ---- conversions + parity weights + cbn (independent, upfront) ----
    {
        CvtJobs j;
        j.s[0] = x;        j.d[0] = xb;    j.n[0] = (size_t)BATCH * 3 * IMG * IMG;
        j.s[1] = patch_w;  j.d[1] = pwb;   j.n[1] = (size_t)DMODEL * 3072;
        j.s[2] = qkv_w;    j.d[2] = qkvwb; j.n[2] = (size_t)LAYERS * 768 * 256;
        j.s[3] = out_w;    j.d[3] = outwb; j.n[3] = (size_t)LAYERS * 256 * 256;
        j.s[4] = ff1_w;    j.d[4] = ff1wb; j.n[4] = (size_t)LAYERS * 1024 * 256;
        j.s[5] = ff2_w;    j.d[5] = ff2wb; j.n[5] = (size_t)LAYERS * 256 * 1024;
        j.s[6] = codebook; j.d[6] = cbb;   j.n[6] = (size_t)KCODES * DMODEL;
        f2bf_multi<<<dim3(512, 7), 256>>>(j);
    }
    {
        WpJobs wj;
        wj.w[0] = dec_w0; wj.wp[0] = wpb + WP0; wj.cin[0] = 256; wj.cout[0] = 256;
        wj.w[1] = dec_w1; wj.wp[1] = wpb + WP1; wj.cin[1] = 256; wj.cout[1] = 128;
        wj.w[2] = dec_w2; wj.wp[2] = wpb + WP2; wj.cin[2] = 128; wj.cout[2] = 64;
        build_wp_multi<<<dim3(1024, 3), 256>>>(wj);
    }
    cbn_kernel<<<KCODES / 8, 256>>>(codebook, cbn);

    // ---- patch embedding ----
    gemm_cp<1, 3, 64, 3><<<dim3(4, 64), 256, SM64>>>(xb, pwb, patch_b, h, hb, nullptr,
                                                     ROWS, DMODEL, 3072, 0, 0);

    // ---- transformer ----
    for (int l = 0; l < LAYERS; l++) {
        gemm_cp<5, 0, 128, 2><<<dim3(6, 64), 256, SM128>>>(hb, qkvwb + (size_t)l * 768 * 256,
                 qkv_b + (size_t)l * 768, nullptr, qkvb, nullptr, ROWS, 768, 256, 0, 0);
        attn_fused<<<NPATCH, 256, ATTN_SMEM>>>(qkvb, attnb);
        gemm_cp<1, 0, 64, 3><<<dim3(4, 64), 256, SM64>>>(attnb, outwb + (size_t)l * 256 * 256,
                 out_b + (size_t)l * 256, proj, nullptr, nullptr, ROWS, 256, 256, 0, 0);
        ln_warp<<<ROWS / 8, 256>>>(h, proj, ln1_w + (size_t)l * 256, ln1_b + (size_t)l * 256, h, hb);
        gemm_cp<2, 0, 128, 2><<<dim3(8, 64), 256, SM128>>>(hb, ff1wb + (size_t)l * 1024 * 256,
                 ff1_b + (size_t)l * 1024, nullptr, midb, nullptr, ROWS, 1024, 256, 0, 0);
        gemm_cp<1, 0, 64, 3><<<dim3(4, 64), 256, SM64>>>(midb, ff2wb + (size_t)l * 256 * 1024,
                 ff2_b + (size_t)l * 256, f2, nullptr, nullptr, ROWS, 256, 1024, 0, 0);
        ln_warp<<<ROWS / 8, 256>>>(h, f2, ln2_w + (size_t)l * 256, ln2_b + (size_t)l * 256, h, hb);
    }
    ln_warp<<<ROWS / 8, 256>>>(h, nullptr, lnf_w, lnf_b, h, hb);

    // ---- VQ ----
    gemm_cp<3, 0, 128, 2><<<dim3(64, 64), 256, SM128>>>(hb, cbb, cbn, tv, nullptr, ti,
                                                        ROWS, KCODES, 256, 0, 0);
    vq_finish<<<ROWS, 256>>>(tv, ti, h, codebook, qdecb, rowloss);

    // ---- decoder: 4-parity-fused NHWC implicit-im2col GEMMs ----
    gemm_cp<4, 2, 128, 2><<<dim3(2, 64, 4), 256, SM128>>>(qdecb, wpb + WP0, dec_b0,
            nullptr, y0b, nullptr, 8192, 256, 1024, 4, 8);
    gemm_cp<4, 2, 128, 2><<<dim3(1, 256, 4), 256, SM128>>>(y0b, wpb + WP1, dec_b1,
            nullptr, y1b, nullptr, 32768, 128, 1024, 5, 8);
    gemm_cp<4, 2, 64, 3><<<dim3(1, 1024, 4), 256, SM64>>>(y1b, wpb + WP2, dec_b2,
            nullptr, y2b, nullptr, 131072, 64, 512, 6, 7);

    // ---- final conv_t + sigmoid -> x_hat ----
    convt_last<<<dim3(BATCH, 16, 16), 256>>>(y2b, dec_w3, dec_b3, (float*)d_out);

    // ---- vq_loss scalar ----
    if (out_size > NXHAT)
        finalize_loss<<<1, 256>>>(rowloss, (float*)d_out + (out_size - 1));
}

// round 17
// speedup vs baseline: 1.0243x; 1.0059x over previous
#include <cuda_runtime.h>
#include <cuda_bf16.h>
#include <math.h>
#include <stdint.h>

typedef __nv_bfloat16 bf16;

#define IMG 512
#define CIN_ 3
#define DMODEL 256
#define KCODES 8192
#define LAYERS 6
#define HEADS 8
#define FFDIM 1024
#define BATCH 32
#define NPATCH 256
#define ROWS 8192
#define NXHAT (BATCH * 3 * 256 * 256)

// ---------------------------------------------------------------------------
// Static scratch
// ---------------------------------------------------------------------------
__device__ float g_h[ROWS * DMODEL];
__device__ float g_proj[ROWS * DMODEL];
__device__ float g_f2[ROWS * DMODEL];
__device__ float g_pk[2 * ROWS * DMODEL];       // patch split-K partials
__device__ float g_cbn[KCODES];
__device__ float g_tv[ROWS * 64];
__device__ int   g_ti[ROWS * 64];
__device__ float g_rowloss[ROWS];

__device__ bf16 g_xb[BATCH * 3 * IMG * IMG];
__device__ bf16 g_pwb[DMODEL * 3072];
__device__ bf16 g_qkvwb[LAYERS * 768 * 256];
__device__ bf16 g_outwb[LAYERS * 256 * 256];
__device__ bf16 g_ff1wb[LAYERS * 1024 * 256];
__device__ bf16 g_ff2wb[LAYERS * 256 * 1024];
__device__ bf16 g_cbb[KCODES * DMODEL];
__device__ bf16 g_wpb[1703936];                 // parity weights, 3 layers
__device__ bf16 g_hb[ROWS * DMODEL];
__device__ bf16 g_qkvb[ROWS * 768];
__device__ bf16 g_attnb[ROWS * DMODEL];
__device__ bf16 g_midb[ROWS * FFDIM];
__device__ bf16 g_qdecb[ROWS * DMODEL];         // NHWC (b,16,16,256)
__device__ bf16 g_y0b[BATCH * 32 * 32 * 256];   // NHWC
__device__ bf16 g_y1b[BATCH * 64 * 64 * 128];   // NHWC
__device__ bf16 g_y2b[BATCH * 128 * 128 * 64];  // NHWC

#define WP0 0
#define WP1 1048576
#define WP2 1572864

// ---------------------------------------------------------------------------
// Helpers
// ---------------------------------------------------------------------------
__device__ __forceinline__ float gelu_exact(float v) {
    return 0.5f * v * (1.0f + erff(v * 0.7071067811865476f));
}
__device__ __forceinline__ uint32_t b2pack(float x, float y) {
    __nv_bfloat162 h = __floats2bfloat162_rn(x, y);
    return *reinterpret_cast<uint32_t*>(&h);
}
__device__ __forceinline__ uint32_t smem_u32(const void* p) {
    uint32_t r;
    asm("{ .reg .u64 t; cvta.to.shared.u64 t, %1; cvt.u32.u64 %0, t; }"
        : "=r"(r) : "l"(p));
    return r;
}
__device__ __forceinline__ void ldm_x4(uint32_t& r0, uint32_t& r1, uint32_t& r2,
                                       uint32_t& r3, uint32_t addr) {
    asm volatile("ldmatrix.sync.aligned.m8n8.x4.shared.b16 {%0,%1,%2,%3}, [%4];"
                 : "=r"(r0), "=r"(r1), "=r"(r2), "=r"(r3) : "r"(addr));
}
__device__ __forceinline__ void mma16816(float* c, const uint32_t* a,
                                         uint32_t b0, uint32_t b1) {
    asm volatile(
        "mma.sync.aligned.m16n8k16.row.col.f32.bf16.bf16.f32 "
        "{%0,%1,%2,%3},{%4,%5,%6,%7},{%8,%9},{%0,%1,%2,%3};"
        : "+f"(c[0]), "+f"(c[1]), "+f"(c[2]), "+f"(c[3])
        : "r"(a[0]), "r"(a[1]), "r"(a[2]), "r"(a[3]), "r"(b0), "r"(b1));
}
__device__ __forceinline__ void cpa16(uint32_t dst, const void* src, int sz) {
    asm volatile("cp.async.cg.shared.global [%0], [%1], 16, %2;"
                 :: "r"(dst), "l"(src), "r"(sz) : "memory");
}
__device__ __forceinline__ void cp_commit() {
    asm volatile("cp.async.commit_group;" ::: "memory");
}
template<int W> __device__ __forceinline__ void cp_wait() {
    asm volatile("cp.async.wait_group %0;" :: "n"(W) : "memory");
}

// ---------------------------------------------------------------------------
// bf16 cp.async 3-stage tensor-core GEMM (K-chunk 32, pitch 40).
//   C[M,N] = A @ B^T
//   AMODE 0: A bf16 row-major M x K.
//   AMODE 2: implicit conv_t im2col over NHWC bf16 (Cin=2^cinlg, Hin=2^hinlg);
//            parity = blockIdx.z; B offset by parity internally.
//   AMODE 3: implicit patch im2col over bf16 x (B,3,512,512).
//            Split-K: blockIdx.z = K-slice; hinlg = koff unit (slice size),
//            cinlg = full B row stride (Kfull).
// EPI: 1 +bias fp32 C (+bf16 Cb if non-null) | 2 +bias+GELU bf16 | 5 +bias bf16 |
//      3 VQ argmin | 4 +bias+ReLU scatter | 6 raw fp32 partial to C + z*M*N.
// MB: min blocks per SM (3 for BN=64, 2 for BN=128).
// ---------------------------------------------------------------------------
template<int EPI, int AMODE, int BN_, int MB>
__global__ void __launch_bounds__(256, MB) gemm_cp(
    const bf16* __restrict__ A, const bf16* __restrict__ B,
    const float* __restrict__ bias, float* __restrict__ C,
    bf16* __restrict__ Cb, int* __restrict__ Ci,
    int M, int N, int K, int hinlg, int cinlg)
{
    constexpr int NT = BN_ / 16;
    extern __shared__ __align__(16) char dynsmem[];
    bf16* Asp = (bf16*)dynsmem;                 // [3][128][40]
    bf16* Bsp = Asp + 3 * 128 * 40;             // [3][BN_][40]
    float* s_val = (float*)(Bsp + 3 * BN_ * 40);
    int*   s_idx = (int*)(s_val + 256);

    const int tid  = threadIdx.x;
    const int lane = tid & 31, warp = tid >> 5;
    const int wm = warp >> 1, wn = warp & 1;
    const int g = lane >> 2, tig = lane & 3;
    const int row0 = blockIdx.y * 128;
    const int col0 = blockIdx.x * BN_;
    const int m_off = wm * 32;
    const int n_off = wn * (BN_ / 2);
    const int pyx = (AMODE == 2) ? blockIdx.z : 0;
    if constexpr (AMODE == 2) B += (size_t)pyx * N * K;
    // AMODE 3 split-K: koff/Kstride; identity elsewhere.
    const int koff = (AMODE == 3) ? (int)blockIdx.z * hinlg : 0;
    const int Kst  = (AMODE == 3) ? cinlg : K;

    const uint32_t as_base = smem_u32(Asp);
    const uint32_t bs_base = smem_u32(Bsp);
    const int a_ld_row = lane & 15;
    const int a_ld_col = (lane >> 4) * 8;
    const int b_ld_row = (lane & 7) + ((lane & 16) ? 8 : 0);
    const int b_ld_col = (lane & 8) ? 8 : 0;

    const int cp_m = tid >> 1;
    const int cp_c = (tid & 1) * 16;

    int am_b = 0, am_jy = 0, am_jx = 0, Hin = 0;
    if constexpr (AMODE == 2) {
        Hin = 1 << hinlg;
        int m = row0 + cp_m;
        am_b = m >> (2 * hinlg);
        int rem = m & ((1 << (2 * hinlg)) - 1);
        am_jy = rem >> hinlg;
        am_jx = rem & (Hin - 1);
    } else if constexpr (AMODE == 3) {
        int m = row0 + cp_m;
        am_b = m >> 8;
        int n = m & 255;
        am_jy = n >> 4;
        am_jx = n & 15;
    }

    float acc[2][NT][4];
#pragma unroll
    for (int i = 0; i < 2; i++)
#pragma unroll
        for (int j = 0; j < NT; j++)
#pragma unroll
            for (int k = 0; k < 4; k++) acc[i][j][k] = 0.f;

    auto copyTile = [&](int buf, int t) {
        const int k0 = t * 32;
        uint32_t adst = as_base + ((uint32_t)(buf * 128 + cp_m) * 40 + cp_c) * 2;
        if constexpr (AMODE == 0) {
            const bf16* s = A + (size_t)(row0 + cp_m) * K + k0 + cp_c;
            cpa16(adst, s, 16);
            cpa16(adst + 16, s + 8, 16);
        } else if constexpr (AMODE == 3) {
            int kk = koff + k0;
            int c  = kk >> 10;
            int py = (kk & 1023) >> 5;
            const bf16* s = A + (((size_t)(am_b * 3 + c) * IMG + am_jy * 32 + py) * IMG
                                 + am_jx * 32 + (kk & 31) + cp_c);
            cpa16(adst, s, 16);
            cpa16(adst + 16, s + 8, 16);
        } else {
            int dd = k0 >> cinlg;
            int ci0 = (k0 & ((1 << cinlg) - 1)) + cp_c;
            int dy = dd >> 1, dx = dd & 1;
            int iy = am_jy - 1 + (pyx >> 1) + dy;
            int ix = am_jx - 1 + (pyx & 1) + dx;
            bool ok = (iy >= 0) & (iy < Hin) & (ix >= 0) & (ix < Hin);
            const bf16* s = ok ? (A + ((((size_t)am_b << hinlg) + iy << hinlg) + ix << cinlg) + ci0)
                               : A;
            int sz = ok ? 16 : 0;
            cpa16(adst, s, sz);
            cpa16(adst + 16, ok ? (s + 8) : s, sz);
        }
        if constexpr (BN_ == 128) {
            uint32_t bdst = bs_base + ((uint32_t)(buf * BN_ + cp_m) * 40 + cp_c) * 2;
            const bf16* s = B + (size_t)(col0 + cp_m) * Kst + koff + k0 + cp_c;
            cpa16(bdst, s, 16);
            cpa16(bdst + 16, s + 8, 16);
        } else {
            uint32_t bdst = bs_base + ((uint32_t)(buf * BN_ + (tid >> 2)) * 40 + (tid & 3) * 8) * 2;
            const bf16* s = B + (size_t)(col0 + (tid >> 2)) * Kst + koff + k0 + (tid & 3) * 8;
            cpa16(bdst, s, 16);
        }
    };

    const int nk = K >> 5;
    copyTile(0, 0); cp_commit();
    copyTile(1, 1); cp_commit();

    int cur = 0, wr = 2;
    for (int t = 0; t < nk; t++) {
        cp_wait<1>();
        __syncthreads();
        if (t + 2 < nk) copyTile(wr, t + 2);
        cp_commit();
#pragma unroll
        for (int ks = 0; ks < 2; ks++) {
            uint32_t af[2][4];
#pragma unroll
            for (int mt = 0; mt < 2; mt++) {
                uint32_t addr = as_base +
                    ((uint32_t)(cur * 128 + m_off + mt * 16 + a_ld_row) * 40 +
                     (uint32_t)(ks * 16 + a_ld_col)) * 2;
                ldm_x4(af[mt][0], af[mt][1], af[mt][2], af[mt][3], addr);
            }
#pragma unroll
            for (int p = 0; p < NT / 2; p++) {
                uint32_t b0, b1, b2, b3;
                uint32_t addr = bs_base +
                    ((uint32_t)(cur * BN_ + n_off + p * 16 + b_ld_row) * 40 +
                     (uint32_t)(ks * 16 + b_ld_col)) * 2;
                ldm_x4(b0, b1, b2, b3, addr);
#pragma unroll
                for (int mt = 0; mt < 2; mt++) {
                    mma16816(acc[mt][2 * p],     af[mt], b0, b1);
                    mma16816(acc[mt][2 * p + 1], af[mt], b2, b3);
                }
            }
        }
        cur = (cur == 2) ? 0 : cur + 1;
        wr  = (wr == 2) ? 0 : wr + 1;
    }

    if constexpr (EPI == 1 || EPI == 2 || EPI == 5) {
#pragma unroll
        for (int mt = 0; mt < 2; mt++)
#pragma unroll
            for (int nt = 0; nt < NT; nt++) {
                int cc = col0 + n_off + nt * 8 + tig * 2;
                float b0v = bias[cc], b1v = bias[cc + 1];
#pragma unroll
                for (int half = 0; half < 2; half++) {
                    int rr = row0 + m_off + mt * 16 + g + half * 8;
                    float v0 = acc[mt][nt][half * 2 + 0] + b0v;
                    float v1 = acc[mt][nt][half * 2 + 1] + b1v;
                    if constexpr (EPI == 2) {
                        v0 = gelu_exact(v0); v1 = gelu_exact(v1);
                        *(uint32_t*)&Cb[(size_t)rr * N + cc] = b2pack(v0, v1);
                    } else if constexpr (EPI == 5) {
                        *(uint32_t*)&Cb[(size_t)rr * N + cc] = b2pack(v0, v1);
                    } else {
                        float2 o; o.x = v0; o.y = v1;
                        *(float2*)&C[(size_t)rr * N + cc] = o;
                        if (Cb)
                            *(uint32_t*)&Cb[(size_t)rr * N + cc] = b2pack(v0, v1);
                    }
                }
            }
    } else if constexpr (EPI == 6) {
        float* Cz = C + (size_t)blockIdx.z * M * N;
#pragma unroll
        for (int mt = 0; mt < 2; mt++)
#pragma unroll
            for (int nt = 0; nt < NT; nt++) {
                int cc = col0 + n_off + nt * 8 + tig * 2;
#pragma unroll
                for (int half = 0; half < 2; half++) {
                    int rr = row0 + m_off + mt * 16 + g + half * 8;
                    float2 o;
                    o.x = acc[mt][nt][half * 2 + 0];
                    o.y = acc[mt][nt][half * 2 + 1];
                    *(float2*)&Cz[(size_t)rr * N + cc] = o;
                }
            }
    } else if constexpr (EPI == 4) {
        const int Hi = 1 << hinlg, Hout = 2 << hinlg;
        const int py = pyx >> 1, px = pyx & 1;
#pragma unroll
        for (int mt = 0; mt < 2; mt++)
#pragma unroll
            for (int half = 0; half < 2; half++) {
                int rr = row0 + m_off + mt * 16 + g + half * 8;
                int b = rr >> (2 * hinlg);
                int rem = rr & ((1 << (2 * hinlg)) - 1);
                int jy = rem >> hinlg, jx = rem & (Hi - 1);
                bf16* orow = Cb + ((size_t)((b * Hout + 2 * jy + py) * Hout + 2 * jx + px)) * N;
#pragma unroll
                for (int nt = 0; nt < NT; nt++) {
                    int cc = col0 + n_off + nt * 8 + tig * 2;
                    float v0 = fmaxf(acc[mt][nt][half * 2 + 0] + bias[cc], 0.f);
                    float v1 = fmaxf(acc[mt][nt][half * 2 + 1] + bias[cc + 1], 0.f);
                    *(uint32_t*)&orow[cc] = b2pack(v0, v1);
                }
            }
    } else { // EPI 3
        float bv[4]; int bi[4];
#pragma unroll
        for (int r = 0; r < 4; r++) { bv[r] = 3.4e38f; bi[r] = 0; }
#pragma unroll
        for (int mt = 0; mt < 2; mt++)
#pragma unroll
            for (int half = 0; half < 2; half++) {
                int r = mt * 2 + half;
#pragma unroll
                for (int nt = 0; nt < NT; nt++)
#pragma unroll
                    for (int q = 0; q < 2; q++) {
                        int cc = col0 + n_off + nt * 8 + tig * 2 + q;
                        float v = bias[cc] - 2.f * acc[mt][nt][half * 2 + q];
                        if (v < bv[r] || (v == bv[r] && cc < bi[r])) { bv[r] = v; bi[r] = cc; }
                    }
            }
#pragma unroll
        for (int off = 1; off <= 2; off <<= 1)
#pragma unroll
            for (int r = 0; r < 4; r++) {
                float ov = __shfl_xor_sync(0xffffffffu, bv[r], off);
                int   oi = __shfl_xor_sync(0xffffffffu, bi[r], off);
                if (ov < bv[r] || (ov == bv[r] && oi < bi[r])) { bv[r] = ov; bi[r] = oi; }
            }
        if (tig == 0) {
#pragma unroll
            for (int r = 0; r < 4; r++) {
                int sr = m_off + (r >> 1) * 16 + g + (r & 1) * 8;
                s_val[wn * 128 + sr] = bv[r];
                s_idx[wn * 128 + sr] = bi[r];
            }
        }
        __syncthreads();
        if (tid < 128) {
            float v0 = s_val[tid], v1 = s_val[128 + tid];
            int   i0 = s_idx[tid], i1 = s_idx[128 + tid];
            if (v1 < v0 || (v1 == v0 && i1 < i0)) { v0 = v1; i0 = i1; }
            C [(size_t)(row0 + tid) * gridDim.x + blockIdx.x] = v0;
            Ci[(size_t)(row0 + tid) * gridDim.x + blockIdx.x] = i0;
        }
    }
}

// ---------------------------------------------------------------------------
// Patch split-K combine: h = pk0 + pk1 + bias (fp32 + bf16 outputs).
// ---------------------------------------------------------------------------
__global__ void __launch_bounds__(256) patch_combine(const float* __restrict__ pk,
                                                     const float* __restrict__ bias,
                                                     float* __restrict__ out,
                                                     bf16* __restrict__ outb)
{
    int lane = threadIdx.x & 31;
    int row = blockIdx.x * 8 + (threadIdx.x >> 5);
#pragma unroll
    for (int half = 0; half < 2; half++) {
        int d = half * 128 + lane * 4;
        size_t off = (size_t)row * DMODEL + d;
        float4 a = *(const float4*)(pk + off);
        float4 b = *(const float4*)(pk + (size_t)ROWS * DMODEL + off);
        float4 bv = *(const float4*)(bias + d);
        float4 o;
        o.x = a.x + b.x + bv.x; o.y = a.y + b.y + bv.y;
        o.z = a.z + b.z + bv.z; o.w = a.w + b.w + bv.w;
        *(float4*)(out + off) = o;
        uint2 p; p.x = b2pack(o.x, o.y); p.y = b2pack(o.z, o.w);
        *(uint2*)(outb + off) = p;
    }
}

// ---------------------------------------------------------------------------
// Batched fp32 -> bf16 convert: gridDim.y selects the job.
// ---------------------------------------------------------------------------
struct CvtJobs {
    const float* s[7];
    bf16* d[7];
    size_t n[7];
};
__global__ void f2bf_multi(CvtJobs j)
{
    const float* __restrict__ src = j.s[blockIdx.y];
    bf16* __restrict__ dst = j.d[blockIdx.y];
    size_t n = j.n[blockIdx.y];
    for (size_t i = ((size_t)blockIdx.x * blockDim.x + threadIdx.x) * 4; i < n;
         i += (size_t)gridDim.x * blockDim.x * 4) {
        float4 v = *(const float4*)(src + i);
        uint2 p;
        p.x = b2pack(v.x, v.y);
        p.y = b2pack(v.z, v.w);
        *(uint2*)(dst + i) = p;
    }
}

// ---------------------------------------------------------------------------
// Batched parity-weight build: gridDim.y selects the decoder layer.
// ---------------------------------------------------------------------------
struct WpJobs {
    const float* w[3];
    bf16* wp[3];
    int cin[3], cout[3];
};
__global__ void build_wp_multi(WpJobs j)
{
    const float* __restrict__ w = j.w[blockIdx.y];
    bf16* __restrict__ wp = j.wp[blockIdx.y];
    int Cin = j.cin[blockIdx.y], Cout = j.cout[blockIdx.y];
    int total = 16 * Cin * Cout;
    for (int i = blockIdx.x * blockDim.x + threadIdx.x; i < total; i += gridDim.x * blockDim.x) {
        int ci = i % Cin;
        int rest = i / Cin;
        int dd = rest & 3;
        int co = (rest >> 2) % Cout;
        int p = (rest >> 2) / Cout;
        int dy = dd >> 1, dx = dd & 1;
        int py = p >> 1, px = p & 1;
        int ky = dy ? (1 - py) : (3 - py);
        int kx = dx ? (1 - px) : (3 - px);
        wp[i] = __float2bfloat16(w[(((size_t)ci * Cout + co) * 4 + ky) * 4 + kx]);
    }
}

// ---------------------------------------------------------------------------
// Fused attention: one block per patch bt, warp = head, warp-private smem.
// K/V bf16 in smem (lossless from bf16 gmem); Q and S fp32. 2 CTAs/SM.
// ---------------------------------------------------------------------------
__global__ void __launch_bounds__(256) attn_fused(const bf16* __restrict__ qkv,
                                                  bf16* __restrict__ o)
{
    extern __shared__ __align__(16) char asmem_raw[];
    const int bt = blockIdx.x;
    const int w = threadIdx.x >> 5, lane = threadIdx.x & 31;
    char* wb = asmem_raw + w * 12672;
    float* Q = (float*)wb;                        // [32][33] fp32
    bf16* Kb = (bf16*)(wb + 4224);                // [32][33] bf16
    bf16* Vb = (bf16*)(wb + 4224 + 2112);         // [32][33] bf16
    float* S = (float*)(wb + 4224 + 2112 + 2112); // [32][33] fp32

#pragma unroll
    for (int s = 0; s < 32; s++) {
        size_t base = ((size_t)s * NPATCH + bt) * 768 + w * 32 + lane;
        Q[s * 33 + lane]  = __bfloat162float(qkv[base]);
        Kb[s * 33 + lane] = qkv[base + 256];
        Vb[s * 33 + lane] = qkv[base + 512];
    }
    __syncwarp();
    {
        float Kr[32];
#pragma unroll
        for (int d = 0; d < 32; d++) Kr[d] = __bfloat162float(Kb[lane * 33 + d]);
#pragma unroll
        for (int s = 0; s < 32; s++) {
            float acc = 0.f;
#pragma unroll
            for (int d = 0; d < 32; d++) acc = fmaf(Q[s * 33 + d], Kr[d], acc);
            S[s * 33 + lane] = acc * 0.17677669529663687f;
        }
    }
    __syncwarp();
    {
        float row[32];
        float m = -3.4e38f;
#pragma unroll
        for (int t = 0; t < 32; t++) { row[t] = S[lane * 33 + t]; m = fmaxf(m, row[t]); }
        float sum = 0.f;
#pragma unroll
        for (int t = 0; t < 32; t++) { row[t] = __expf(row[t] - m); sum += row[t]; }
        float inv = 1.f / sum;
#pragma unroll
        for (int t = 0; t < 32; t++) S[lane * 33 + t] = row[t] * inv;
    }
    __syncwarp();
    {
        float Vr[32];
#pragma unroll
        for (int t = 0; t < 32; t++) Vr[t] = __bfloat162float(Vb[t * 33 + lane]);
#pragma unroll
        for (int s = 0; s < 32; s++) {
            float acc = 0.f;
#pragma unroll
            for (int t = 0; t < 32; t++) acc = fmaf(S[s * 33 + t], Vr[t], acc);
            o[((size_t)s * NPATCH + bt) * DMODEL + w * 32 + lane] = __float2bfloat16(acc);
        }
    }
}
#define ATTN_SMEM 101376

// ---------------------------------------------------------------------------
// Warp-per-row LayerNorm over D=256; dual fp32 + bf16 output.
// ---------------------------------------------------------------------------
__global__ void __launch_bounds__(256) ln_warp(const float* __restrict__ x,
                                               const float* __restrict__ r,
                                               const float* __restrict__ g,
                                               const float* __restrict__ b,
                                               float* __restrict__ out,
                                               bf16* __restrict__ outb)
{
    int lane = threadIdx.x & 31;
    int row = blockIdx.x * 8 + (threadIdx.x >> 5);
    const float* xr = x + (size_t)row * DMODEL;
    int d0 = lane * 4, d1 = 128 + lane * 4;
    float4 v0 = *(const float4*)(xr + d0);
    float4 v1 = *(const float4*)(xr + d1);
    if (r) {
        const float* rr = r + (size_t)row * DMODEL;
        float4 a0 = *(const float4*)(rr + d0);
        float4 a1 = *(const float4*)(rr + d1);
        v0.x += a0.x; v0.y += a0.y; v0.z += a0.z; v0.w += a0.w;
        v1.x += a1.x; v1.y += a1.y; v1.z += a1.z; v1.w += a1.w;
    }
    float s = v0.x + v0.y + v0.z + v0.w + v1.x + v1.y + v1.z + v1.w;
#pragma unroll
    for (int off = 16; off; off >>= 1) s += __shfl_xor_sync(0xffffffffu, s, off);
    float mean = s * (1.f / DMODEL);
    float c0x = v0.x - mean, c0y = v0.y - mean, c0z = v0.z - mean, c0w = v0.w - mean;
    float c1x = v1.x - mean, c1y = v1.y - mean, c1z = v1.z - mean, c1w = v1.w - mean;
    float ss = c0x*c0x + c0y*c0y + c0z*c0z + c0w*c0w
             + c1x*c1x + c1y*c1y + c1z*c1z + c1w*c1w;
#pragma unroll
    for (int off = 16; off; off >>= 1) ss += __shfl_xor_sync(0xffffffffu, ss, off);
    float inv = rsqrtf(ss * (1.f / DMODEL) + 1e-5f);
    float4 g0 = *(const float4*)(g + d0), g1 = *(const float4*)(g + d1);
    float4 b0 = *(const float4*)(b + d0), b1 = *(const float4*)(b + d1);
    float4 o0, o1;
    o0.x = c0x * inv * g0.x + b0.x; o0.y = c0y * inv * g0.y + b0.y;
    o0.z = c0z * inv * g0.z + b0.z; o0.w = c0w * inv * g0.w + b0.w;
    o1.x = c1x * inv * g1.x + b1.x; o1.y = c1y * inv * g1.y + b1.y;
    o1.z = c1z * inv * g1.z + b1.z; o1.w = c1w * inv * g1.w + b1.w;
    float* orow = out + (size_t)row * DMODEL;
    *(float4*)(orow + d0) = o0;
    *(float4*)(orow + d1) = o1;
    if (outb) {
        bf16* obr = outb + (size_t)row * DMODEL;
        uint2 p0, p1;
        p0.x = b2pack(o0.x, o0.y); p0.y = b2pack(o0.z, o0.w);
        p1.x = b2pack(o1.x, o1.y); p1.y = b2pack(o1.z, o1.w);
        *(uint2*)(obr + d0) = p0;
        *(uint2*)(obr + d1) = p1;
    }
}

// ---------------------------------------------------------------------------
// VQ helpers
// ---------------------------------------------------------------------------
__global__ void __launch_bounds__(256) cbn_kernel(const float* __restrict__ cb,
                                                  float* __restrict__ cbn)
{
    int lane = threadIdx.x & 31;
    int k = blockIdx.x * 8 + (threadIdx.x >> 5);
    const float* row = cb + (size_t)k * DMODEL;
    float s = 0.f;
#pragma unroll
    for (int i = 0; i < 2; i++) {
        float4 v = *(const float4*)(row + lane * 4 + i * 128);
        s += v.x * v.x + v.y * v.y + v.z * v.z + v.w * v.w;
    }
#pragma unroll
    for (int off = 16; off; off >>= 1) s += __shfl_xor_sync(0xffffffffu, s, off);
    if (lane == 0) cbn[k] = s;
}

// Warp-per-row final-argmin + gather + loss (8 rows/block, no block barriers).
__global__ void __launch_bounds__(256) vq_finish(const float* __restrict__ tv,
                                                 const int* __restrict__ ti,
                                                 const float* __restrict__ h,
                                                 const float* __restrict__ cb,
                                                 bf16* __restrict__ qdecb,
                                                 float* __restrict__ rowloss)
{
    int lane = threadIdx.x & 31;
    int row = blockIdx.x * 8 + (threadIdx.x >> 5);
    // argmin over 64 tile candidates
    float v  = tv[row * 64 + lane];      int i  = ti[row * 64 + lane];
    float v2 = tv[row * 64 + 32 + lane]; int i2 = ti[row * 64 + 32 + lane];
    if (v2 < v || (v2 == v && i2 < i)) { v = v2; i = i2; }
#pragma unroll
    for (int off = 16; off; off >>= 1) {
        float ov = __shfl_xor_sync(0xffffffffu, v, off);
        int   oi = __shfl_xor_sync(0xffffffffu, i, off);
        if (ov < v || (ov == v && oi < i)) { v = ov; i = oi; }
    }
    int code = __shfl_sync(0xffffffffu, i, 0);
    // gather + loss: lane owns 8 contiguous dims
    const float* q8 = cb + (size_t)code * DMODEL + lane * 8;
    const float* h8 = h + (size_t)row * DMODEL + lane * 8;
    float ls = 0.f;
    bf16 qb[8];
#pragma unroll
    for (int j = 0; j < 8; j += 4) {
        float4 qv = *(const float4*)(q8 + j);
        float4 hv = *(const float4*)(h8 + j);
        qb[j + 0] = __float2bfloat16(qv.x);
        qb[j + 1] = __float2bfloat16(qv.y);
        qb[j + 2] = __float2bfloat16(qv.z);
        qb[j + 3] = __float2bfloat16(qv.w);
        float dx = qv.x - hv.x, dy = qv.y - hv.y, dz = qv.z - hv.z, dw = qv.w - hv.w;
        ls += dx * dx + dy * dy + dz * dz + dw * dw;
    }
    *(uint4*)(qdecb + (size_t)row * DMODEL + lane * 8) = *(uint4*)qb;
#pragma unroll
    for (int off = 16; off; off >>= 1) ls += __shfl_xor_sync(0xffffffffu, ls, off);
    if (lane == 0) rowloss[row] = ls;
}

__global__ void __launch_bounds__(256) finalize_loss(const float* __restrict__ rowloss,
                                                     float* __restrict__ out_loss)
{
    __shared__ float red[256];
    float s = 0.f;
    for (int i = threadIdx.x; i < ROWS; i += 256) s += rowloss[i];
    red[threadIdx.x] = s; __syncthreads();
    for (int st = 128; st; st >>= 1) { if (threadIdx.x < st) red[threadIdx.x] += red[threadIdx.x + st]; __syncthreads(); }
    if (threadIdx.x == 0) *out_loss = 1.25f * red[0] / (float)((size_t)ROWS * DMODEL);
}

// Final layer (Cin=64 NHWC bf16, Cout=3, 128->256, sigmoid)
__global__ void __launch_bounds__(256) convt_last(const bf16* __restrict__ in,
                                                  const float* __restrict__ w,
                                                  const float* __restrict__ bias,
                                                  float* __restrict__ out)
{
    __shared__ float ws[64 * 3 * 16];
    int tid = threadIdx.x;
    for (int i = tid; i < 64 * 3 * 16; i += 256) ws[i] = w[i];
    __syncthreads();
    int b = blockIdx.x;
    int oy = blockIdx.y * 16 + (tid >> 4);
    int ox = blockIdx.z * 16 + (tid & 15);
    int py = oy & 1, px = ox & 1;
    int jy = oy >> 1, jx = ox >> 1;
    int kys[2] = {3 - py, 1 - py};
    int kxs[2] = {3 - px, 1 - px};
    int iys[2] = {jy - 1 + py, jy + py};
    int ixs[2] = {jx - 1 + px, jx + px};
    float acc[3] = {bias[0], bias[1], bias[2]};
#pragma unroll
    for (int ty = 0; ty < 2; ty++) {
        int iy = iys[ty];
        if (iy < 0 || iy >= 128) continue;
#pragma unroll
        for (int tx = 0; tx < 2; tx++) {
            int ix = ixs[tx];
            if (ix < 0 || ix >= 128) continue;
            const bf16* p = in + ((size_t)(b * 128 + iy) * 128 + ix) * 64;
            int wo = kys[ty] * 4 + kxs[tx];
            for (int c8 = 0; c8 < 64; c8 += 8) {
                uint4 v = *(const uint4*)(p + c8);
                const bf16* e = (const bf16*)&v;
#pragma unroll
                for (int j = 0; j < 8; j++) {
                    float f = __bfloat162float(e[j]);
                    const float* wr = ws + (c8 + j) * 48 + wo;
                    acc[0] = fmaf(f, wr[0],  acc[0]);
                    acc[1] = fmaf(f, wr[16], acc[1]);
                    acc[2] = fmaf(f, wr[32], acc[2]);
                }
            }
        }
    }
#pragma unroll
    for (int co = 0; co < 3; co++)
        out[(((size_t)b * 3 + co) * 256 + oy) * 256 + ox] = 1.f / (1.f + __expf(-acc[co]));
}

// ---------------------------------------------------------------------------
// Host driver (round-16 proven config + patch split-K + warp vq_finish)
// ---------------------------------------------------------------------------
#define SM128 (3*128*40*2 + 3*128*40*2 + 2048)
#define SM64  (3*128*40*2 + 3*64*40*2 + 2048)

extern "C" void kernel_launch(void* const* d_in, const int* in_sizes, int n_in,
                              void* d_out, int out_size)
{
    const float* x       = (const float*)d_in[0];
    const float* patch_w = (const float*)d_in[1];
    const float* patch_b = (const float*)d_in[2];
    const float* qkv_w   = (const float*)d_in[3];
    const float* qkv_b   = (const float*)d_in[4];
    const float* out_w   = (const float*)d_in[5];
    const float* out_b   = (const float*)d_in[6];
    const float* ln1_w   = (const float*)d_in[7];
    const float* ln1_b   = (const float*)d_in[8];
    const float* ln2_w   = (const float*)d_in[9];
    const float* ln2_b   = (const float*)d_in[10];
    const float* ff1_w   = (const float*)d_in[11];
    const float* ff1_b   = (const float*)d_in[12];
    const float* ff2_w   = (const float*)d_in[13];
    const float* ff2_b   = (const float*)d_in[14];
    const float* lnf_w   = (const float*)d_in[15];
    const float* lnf_b   = (const float*)d_in[16];
    const float* codebook= (const float*)d_in[17];
    const float* dec_w0  = (const float*)d_in[18];
    const float* dec_b0  = (const float*)d_in[19];
    const float* dec_w1  = (const float*)d_in[20];
    const float* dec_b1  = (const float*)d_in[21];
    const float* dec_w2  = (const float*)d_in[22];
    const float* dec_b2  = (const float*)d_in[23];
    const float* dec_w3  = (const float*)d_in[24];
    const float* dec_b3  = (const float*)d_in[25];

    float *h, *proj, *f2, *pk, *cbn, *tv, *rowloss;
    bf16 *xb, *pwb, *qkvwb, *outwb, *ff1wb, *ff2wb, *cbb, *wpb;
    bf16 *hb, *qkvb, *attnb, *midb, *qdecb, *y0b, *y1b, *y2b;
    int *ti;
    cudaGetSymbolAddress((void**)&h, g_h);
    cudaGetSymbolAddress((void**)&proj, g_proj);
    cudaGetSymbolAddress((void**)&f2, g_f2);
    cudaGetSymbolAddress((void**)&pk, g_pk);
    cudaGetSymbolAddress((void**)&cbn, g_cbn);
    cudaGetSymbolAddress((void**)&tv, g_tv);
    cudaGetSymbolAddress((void**)&ti, g_ti);
    cudaGetSymbolAddress((void**)&rowloss, g_rowloss);
    cudaGetSymbolAddress((void**)&xb, g_xb);
    cudaGetSymbolAddress((void**)&pwb, g_pwb);
    cudaGetSymbolAddress((void**)&qkvwb, g_qkvwb);
    cudaGetSymbolAddress((void**)&outwb, g_outwb);
    cudaGetSymbolAddress((void**)&ff1wb, g_ff1wb);
    cudaGetSymbolAddress((void**)&ff2wb, g_ff2wb);
    cudaGetSymbolAddress((void**)&cbb, g_cbb);
    cudaGetSymbolAddress((void**)&wpb, g_wpb);
    cudaGetSymbolAddress((void**)&hb, g_hb);
    cudaGetSymbolAddress((void**)&qkvb, g_qkvb);
    cudaGetSymbolAddress((void**)&attnb, g_attnb);
    cudaGetSymbolAddress((void**)&midb, g_midb);
    cudaGetSymbolAddress((void**)&qdecb, g_qdecb);
    cudaGetSymbolAddress((void**)&y0b, g_y0b);
    cudaGetSymbolAddress((void**)&y1b, g_y1b);
    cudaGetSymbolAddress((void**)&y2b, g_y2b);

    cudaFuncSetAttribute(gemm_cp<6,3,64,3>,  cudaFuncAttributeMaxDynamicSharedMemorySize, SM64);
    cudaFuncSetAttribute(gemm_cp<5,0,128,2>, cudaFuncAttributeMaxDynamicSharedMemorySize, SM128);
    cudaFuncSetAttribute(gemm_cp<1,0,64,3>,  cudaFuncAttributeMaxDynamicSharedMemorySize, SM64);
    cudaFuncSetAttribute(gemm_cp<2,0,128,2>, cudaFuncAttributeMaxDynamicSharedMemorySize, SM128);
    cudaFuncSetAttribute(gemm_cp<3,0,128,2>, cudaFuncAttributeMaxDynamicSharedMemorySize, SM128);
    cudaFuncSetAttribute(gemm_cp<4,2,128,2>, cudaFuncAttributeMaxDynamicSharedMemorySize, SM128);
    cudaFuncSetAttribute(gemm_cp<4,2,64,3>,  cudaFuncAttributeMaxDynamicSharedMemorySize, SM64);
    cudaFuncSetAttribute(attn_fused,         cudaFuncAttributeMaxDynamicSharedMemorySize, ATTN_SMEM);

    // ---- conversions + parity weights + cbn (independent, upfront) ----
    {
        CvtJobs j;
        j.s[0] = x;        j.d[0] = xb;    j.n[0] = (size_t)BATCH * 3 * IMG * IMG;
        j.s[1] = patch_w;  j.d[1] = pwb;   j.n[1] = (size_t)DMODEL * 3072;
        j.s[2] = qkv_w;    j.d[2] = qkvwb; j.n[2] = (size_t)LAYERS * 768 * 256;
        j.s[3] = out_w;    j.d[3] = outwb; j.n[3] = (size_t)LAYERS * 256 * 256;
        j.s[4] = ff1_w;    j.d[4] = ff1wb; j.n[4] = (size_t)LAYERS * 1024 * 256;
        j.s[5] = ff2_w;    j.d[5] = ff2wb; j.n[5] = (size_t)LAYERS * 256 * 1024;
        j.s[6] = codebook; j.d[6] = cbb;   j.n[6] = (size_t)KCODES * DMODEL;
        f2bf_multi<<<dim3(512, 7), 256>>>(j);
    }
    {
        WpJobs wj;
        wj.w[0] = dec_w0; wj.wp[0] = wpb + WP0; wj.cin[0] = 256; wj.cout[0] = 256;
        wj.w[1] = dec_w1; wj.wp[1] = wpb + WP1; wj.cin[1] = 256; wj.cout[1] = 128;
        wj.w[2] = dec_w2; wj.wp[2] = wpb + WP2; wj.cin[2] = 128; wj.cout[2] = 64;
        build_wp_multi<<<dim3(1024, 3), 256>>>(wj);
    }
    cbn_kernel<<<KCODES / 8, 256>>>(codebook, cbn);

    // ---- patch embedding: split-K=2 (z = K-half), raw partials + combine ----
    gemm_cp<6, 3, 64, 3><<<dim3(4, 64, 2), 256, SM64>>>(xb, pwb, nullptr, pk, nullptr,
            nullptr, ROWS, DMODEL, 1536, 1536, 3072);
    patch_combine<<<ROWS / 8, 256>>>(pk, patch_b, h, hb);

    // ---- transformer ----
    for (int l = 0; l < LAYERS; l++) {
        gemm_cp<5, 0, 128, 2><<<dim3(6, 64), 256, SM128>>>(hb, qkvwb + (size_t)l * 768 * 256,
                 qkv_b + (size_t)l * 768, nullptr, qkvb, nullptr, ROWS, 768, 256, 0, 0);
        attn_fused<<<NPATCH, 256, ATTN_SMEM>>>(qkvb, attnb);
        gemm_cp<1, 0, 64, 3><<<dim3(4, 64), 256, SM64>>>(attnb, outwb + (size_t)l * 256 * 256,
                 out_b + (size_t)l * 256, proj, nullptr, nullptr, ROWS, 256, 256, 0, 0);
        ln_warp<<<ROWS / 8, 256>>>(h, proj, ln1_w + (size_t)l * 256, ln1_b + (size_t)l * 256, h, hb);
        gemm_cp<2, 0, 128, 2><<<dim3(8, 64), 256, SM128>>>(hb, ff1wb + (size_t)l * 1024 * 256,
                 ff1_b + (size_t)l * 1024, nullptr, midb, nullptr, ROWS, 1024, 256, 0, 0);
        gemm_cp<1, 0, 64, 3><<<dim3(4, 64), 256, SM64>>>(midb, ff2wb + (size_t)l * 256 * 1024,
                 ff2_b + (size_t)l * 256, f2, nullptr, nullptr, ROWS, 256, 1024, 0, 0);
        ln_warp<<<ROWS / 8, 256>>>(h, f2, ln2_w + (size_t)l * 256, ln2_b + (size_t)l * 256, h, hb);
    }
    ln_warp<<<ROWS / 8, 256>>>(h, nullptr, lnf_w, lnf_b, h, hb);

    // ---- VQ ----
    gemm_cp<3, 0, 128, 2><<<dim3(64, 64), 256, SM128>>>(hb, cbb, cbn, tv, nullptr, ti,
                                                        ROWS, KCODES, 256, 0, 0);
    vq_finish<<<ROWS / 8, 256>>>(tv, ti, h, codebook, qdecb, rowloss);

    // ---- decoder: 4-parity-fused NHWC implicit-im2col GEMMs ----
    gemm_cp<4, 2, 128, 2><<<dim3(2, 64, 4), 256, SM128>>>(qdecb, wpb + WP0, dec_b0,
            nullptr, y0b, nullptr, 8192, 256, 1024, 4, 8);
    gemm_cp<4, 2, 128, 2><<<dim3(1, 256, 4), 256, SM128>>>(y0b, wpb + WP1, dec_b1,
            nullptr, y1b, nullptr, 32768, 128, 1024, 5, 8);
    gemm_cp<4, 2, 64, 3><<<dim3(1, 1024, 4), 256, SM64>>>(y1b, wpb + WP2, dec_b2,
            nullptr, y2b, nullptr, 131072, 64, 512, 6, 7);

    // ---- final conv_t + sigmoid -> x_hat ----
    convt_last<<<dim3(BATCH, 16, 16), 256>>>(y2b, dec_w3, dec_b3, (float*)d_out);

    // ---- vq_loss scalar ----
    if (out_size > NXHAT)
        finalize_loss<<<1, 256>>>(rowloss, (float*)d_out + (out_size - 1));
}